// round 3
// baseline (speedup 1.0000x reference)
#include <cuda_runtime.h>
#include <cstddef>

#define BN_EPS 1e-5f

// Scratch (device globals — no allocation allowed)
__device__ float g_q[4 * 64 * 4096];
__device__ float g_k[4 * 64 * 4096];
__device__ float g_v[4 * 64 * 4096];
__device__ float g_f[4 * 64 * 4096];

// ---------------------------------------------------------------------------
// 3x3 conv (pad=1) + folded BN + ReLU (+ optional residual add), NCHW, 64x64.
// grid: (16 pixel tiles of 16x16, cout_total/OC, B); block: 256 threads (1/px)
// Each thread accumulates OC output channels in registers.
// ---------------------------------------------------------------------------
template <int CIN, int OC, bool RESID>
__global__ void __launch_bounds__(256)
conv3x3_bn_relu(const float* __restrict__ in,
                const float* __restrict__ w,
                const float* __restrict__ cb,
                const float* __restrict__ cg,
                const float* __restrict__ cbe,
                const float* __restrict__ cm,
                const float* __restrict__ cv,
                const float* __restrict__ resid,
                float* __restrict__ out,
                int cout_total)
{
    const int tid    = threadIdx.x;
    const int tile   = blockIdx.x;
    const int ocbase = blockIdx.y * OC;
    const int b      = blockIdx.z;
    const int ty0 = (tile >> 2) * 16;
    const int tx0 = (tile & 3) * 16;
    const int px = tid & 15, py = tid >> 4;
    const int oy = ty0 + py, ox = tx0 + px;

    __shared__ float s_in[18 * 18];
    __shared__ float s_w[OC * 12];  // padded rows for float4 reads

    float acc[OC];
#pragma unroll
    for (int o = 0; o < OC; o++) acc[o] = 0.f;

    const float* ip0 = in + (((size_t)b * CIN) << 12);

    for (int ic = 0; ic < CIN; ic++) {
        __syncthreads();
        const float* ip = ip0 + ((size_t)ic << 12);
        for (int i = tid; i < 18 * 18; i += 256) {
            int r = i / 18, c = i - r * 18;
            int gy = ty0 - 1 + r, gx = tx0 - 1 + c;
            float v = 0.f;
            if ((unsigned)gy < 64u && (unsigned)gx < 64u) v = ip[(gy << 6) + gx];
            s_in[i] = v;
        }
        for (int i = tid; i < OC * 9; i += 256) {
            int o = i / 9, k = i - o * 9;
            s_w[o * 12 + k] = w[((size_t)(ocbase + o) * CIN + ic) * 9 + k];
        }
        __syncthreads();

        float nb[9];
#pragma unroll
        for (int r = 0; r < 3; r++)
#pragma unroll
            for (int c = 0; c < 3; c++)
                nb[r * 3 + c] = s_in[(py + r) * 18 + px + c];

#pragma unroll
        for (int o = 0; o < OC; o++) {
            const float4 w0 = *(const float4*)&s_w[o * 12];
            const float4 w1 = *(const float4*)&s_w[o * 12 + 4];
            const float  w8 = s_w[o * 12 + 8];
            float a = acc[o];
            a = fmaf(nb[0], w0.x, a);
            a = fmaf(nb[1], w0.y, a);
            a = fmaf(nb[2], w0.z, a);
            a = fmaf(nb[3], w0.w, a);
            a = fmaf(nb[4], w1.x, a);
            a = fmaf(nb[5], w1.y, a);
            a = fmaf(nb[6], w1.z, a);
            a = fmaf(nb[7], w1.w, a);
            a = fmaf(nb[8], w8,  a);
            acc[o] = a;
        }
    }

#pragma unroll
    for (int o = 0; o < OC; o++) {
        int oc = ocbase + o;
        float inv = cg[oc] * rsqrtf(cv[oc] + BN_EPS);
        float bb  = fmaf(cb[oc], inv, cbe[oc] - cm[oc] * inv);
        float y   = fmaxf(fmaf(acc[o], inv, bb), 0.f);
        size_t gi = (((size_t)b * cout_total + oc) << 12) + (oy << 6) + ox;
        if (RESID) y += resid[gi];
        out[gi] = y;
    }
}

// ---------------------------------------------------------------------------
// Flash attention over q,k,v device buffers (layout [b][c][n], c=d=64, N=4096)
// grid: (64 n-tiles, 4 batches); block 256 threads (16x16, 4x4 fragments)
// Dynamic smem: Qs[64][64] + Ks[64][64] + Vs[64][68] + Ps[64][68] = 67584 B
// ---------------------------------------------------------------------------
__global__ void __launch_bounds__(256) attn_kernel()
{
    extern __shared__ float sm[];
    float* Qs = sm;                  // [d][n], stride 64
    float* Ks = Qs + 64 * 64;        // [d][m], stride 64
    float* Vs = Ks + 64 * 64;        // [m][c], stride 68 (padded)
    float* Ps = Vs + 64 * 68;        // [m][n], stride 68 (padded)

    const int tid = threadIdx.x;
    const int tx = tid & 15, ty = tid >> 4;
    const int tn = ty << 2, tm = tx << 2, tc = tx << 2;
    const int b  = blockIdx.y;
    const int n0 = blockIdx.x << 6;

    const float* qp = g_q + ((size_t)b << 18) + n0;
    const float* kp = g_k + ((size_t)b << 18);
    const float* vp = g_v + ((size_t)b << 18);

    for (int e = tid; e < 4096; e += 256)
        Qs[e] = qp[((e >> 6) << 12) + (e & 63)];

    float o[4][4];
    float mi[4], li[4];
#pragma unroll
    for (int i = 0; i < 4; i++) {
        mi[i] = -1e30f; li[i] = 0.f;
#pragma unroll
        for (int j = 0; j < 4; j++) o[i][j] = 0.f;
    }

    for (int t = 0; t < 64; t++) {
        __syncthreads();   // prev PV done before overwriting Ks/Vs; also covers Qs on t=0
        const int m0 = t << 6;
        for (int e = tid; e < 4096; e += 256) {
            int c = e >> 6, m = e & 63;
            float kv = kp[(c << 12) + m0 + m];
            float vv = vp[(c << 12) + m0 + m];
            Ks[e] = kv;              // [c][m]
            Vs[m * 68 + c] = vv;     // transposed
        }
        __syncthreads();

        // S = Q^T K (64x64 tile, 4x4 per thread)
        float s[4][4];
#pragma unroll
        for (int i = 0; i < 4; i++)
#pragma unroll
            for (int j = 0; j < 4; j++) s[i][j] = 0.f;

#pragma unroll 8
        for (int d = 0; d < 64; d++) {
            float4 qv = *(const float4*)&Qs[(d << 6) + tn];
            float4 kv = *(const float4*)&Ks[(d << 6) + tm];
            s[0][0] = fmaf(qv.x, kv.x, s[0][0]);
            s[0][1] = fmaf(qv.x, kv.y, s[0][1]);
            s[0][2] = fmaf(qv.x, kv.z, s[0][2]);
            s[0][3] = fmaf(qv.x, kv.w, s[0][3]);
            s[1][0] = fmaf(qv.y, kv.x, s[1][0]);
            s[1][1] = fmaf(qv.y, kv.y, s[1][1]);
            s[1][2] = fmaf(qv.y, kv.z, s[1][2]);
            s[1][3] = fmaf(qv.y, kv.w, s[1][3]);
            s[2][0] = fmaf(qv.z, kv.x, s[2][0]);
            s[2][1] = fmaf(qv.z, kv.y, s[2][1]);
            s[2][2] = fmaf(qv.z, kv.z, s[2][2]);
            s[2][3] = fmaf(qv.z, kv.w, s[2][3]);
            s[3][0] = fmaf(qv.w, kv.x, s[3][0]);
            s[3][1] = fmaf(qv.w, kv.y, s[3][1]);
            s[3][2] = fmaf(qv.w, kv.z, s[3][2]);
            s[3][3] = fmaf(qv.w, kv.w, s[3][3]);
        }

        // Online softmax. Rows tn..tn+3 are shared by the 16 lanes with equal ty;
        // lane = (ty&1)*16 + tx, so xor offsets 1,2,4,8 reduce within that group.
        float rmax[4];
#pragma unroll
        for (int i = 0; i < 4; i++)
            rmax[i] = fmaxf(fmaxf(s[i][0], s[i][1]), fmaxf(s[i][2], s[i][3]));
#pragma unroll
        for (int off = 8; off >= 1; off >>= 1)
#pragma unroll
            for (int i = 0; i < 4; i++)
                rmax[i] = fmaxf(rmax[i], __shfl_xor_sync(0xffffffffu, rmax[i], off));

        float corr[4], rsum[4];
#pragma unroll
        for (int i = 0; i < 4; i++) {
            float mn = fmaxf(mi[i], rmax[i]);
            corr[i] = __expf(mi[i] - mn);
            mi[i] = mn;
            rsum[i] = 0.f;
        }
#pragma unroll
        for (int i = 0; i < 4; i++)
#pragma unroll
            for (int j = 0; j < 4; j++) {
                float p = __expf(s[i][j] - mi[i]);
                s[i][j] = p;
                rsum[i] += p;
            }
#pragma unroll
        for (int off = 8; off >= 1; off >>= 1)
#pragma unroll
            for (int i = 0; i < 4; i++)
                rsum[i] += __shfl_xor_sync(0xffffffffu, rsum[i], off);
#pragma unroll
        for (int i = 0; i < 4; i++) {
            li[i] = li[i] * corr[i] + rsum[i];
#pragma unroll
            for (int j = 0; j < 4; j++) o[i][j] *= corr[i];
        }

        // Stage P as [m][n] for the PV GEMM
#pragma unroll
        for (int j = 0; j < 4; j++)
#pragma unroll
            for (int i = 0; i < 4; i++)
                Ps[(tm + j) * 68 + tn + i] = s[i][j];
        __syncthreads();

        // O += P V   (P[m][n] x V[m][c], both float4 rows)
#pragma unroll 8
        for (int m = 0; m < 64; m++) {
            float4 pv = *(const float4*)&Ps[m * 68 + tn];
            float4 vv = *(const float4*)&Vs[m * 68 + tc];
            o[0][0] = fmaf(pv.x, vv.x, o[0][0]);
            o[0][1] = fmaf(pv.x, vv.y, o[0][1]);
            o[0][2] = fmaf(pv.x, vv.z, o[0][2]);
            o[0][3] = fmaf(pv.x, vv.w, o[0][3]);
            o[1][0] = fmaf(pv.y, vv.x, o[1][0]);
            o[1][1] = fmaf(pv.y, vv.y, o[1][1]);
            o[1][2] = fmaf(pv.y, vv.z, o[1][2]);
            o[1][3] = fmaf(pv.y, vv.w, o[1][3]);
            o[2][0] = fmaf(pv.z, vv.x, o[2][0]);
            o[2][1] = fmaf(pv.z, vv.y, o[2][1]);
            o[2][2] = fmaf(pv.z, vv.z, o[2][2]);
            o[2][3] = fmaf(pv.z, vv.w, o[2][3]);
            o[3][0] = fmaf(pv.w, vv.x, o[3][0]);
            o[3][1] = fmaf(pv.w, vv.y, o[3][1]);
            o[3][2] = fmaf(pv.w, vv.z, o[3][2]);
            o[3][3] = fmaf(pv.w, vv.w, o[3][3]);
        }
    }

    // Normalize and write f[b][c][n]
#pragma unroll
    for (int i = 0; i < 4; i++) {
        float invl = 1.f / li[i];
#pragma unroll
        for (int j = 0; j < 4; j++)
            g_f[((size_t)(b * 64 + tc + j) << 12) + n0 + tn + i] = o[i][j] * invl;
    }
}

// ---------------------------------------------------------------------------
extern "C" void kernel_launch(void* const* d_in, const int* in_sizes, int n_in,
                              void* d_out, int out_size)
{
    (void)in_sizes; (void)n_in; (void)out_size;

    const float* f1  = (const float*)d_in[0];
    const float* f2  = (const float*)d_in[1];
    const float* qw  = (const float*)d_in[2];
    const float* qb  = (const float*)d_in[3];
    const float* qg  = (const float*)d_in[4];
    const float* qbe = (const float*)d_in[5];
    const float* qm  = (const float*)d_in[6];
    const float* qv  = (const float*)d_in[7];
    const float* kw  = (const float*)d_in[8];
    const float* kb  = (const float*)d_in[9];
    const float* kg  = (const float*)d_in[10];
    const float* kbe = (const float*)d_in[11];
    const float* km  = (const float*)d_in[12];
    const float* kv  = (const float*)d_in[13];
    const float* vw  = (const float*)d_in[14];
    const float* vb  = (const float*)d_in[15];
    const float* vg  = (const float*)d_in[16];
    const float* vbe = (const float*)d_in[17];
    const float* vm  = (const float*)d_in[18];
    const float* vv  = (const float*)d_in[19];
    const float* rw  = (const float*)d_in[20];
    const float* rb  = (const float*)d_in[21];
    const float* rg  = (const float*)d_in[22];
    const float* rbe = (const float*)d_in[23];
    const float* rm  = (const float*)d_in[24];
    const float* rv  = (const float*)d_in[25];
    float* out = (float*)d_out;

    float *pq, *pk, *pv, *pf;
    cudaGetSymbolAddress((void**)&pq, g_q);
    cudaGetSymbolAddress((void**)&pk, g_k);
    cudaGetSymbolAddress((void**)&pv, g_v);
    cudaGetSymbolAddress((void**)&pf, g_f);

    dim3 blk(256);
    // q = conv_bn_relu(feature2), k/v = conv_bn_relu(feature1)
    conv3x3_bn_relu<256, 64, false><<<dim3(16, 1, 4), blk>>>(
        f2, qw, qb, qg, qbe, qm, qv, nullptr, pq, 64);
    conv3x3_bn_relu<256, 64, false><<<dim3(16, 1, 4), blk>>>(
        f1, kw, kb, kg, kbe, km, kv, nullptr, pk, 64);
    conv3x3_bn_relu<256, 64, false><<<dim3(16, 1, 4), blk>>>(
        f1, vw, vb, vg, vbe, vm, vv, nullptr, pv, 64);

    const int attn_smem = (64 * 64 + 64 * 64 + 64 * 68 + 64 * 68) * (int)sizeof(float);
    cudaFuncSetAttribute(attn_kernel,
                         cudaFuncAttributeMaxDynamicSharedMemorySize, attn_smem);
    attn_kernel<<<dim3(64, 4), blk, attn_smem>>>();

    // out = feature1 + conv_bn_relu(f)
    conv3x3_bn_relu<64, 64, true><<<dim3(16, 4, 4), blk>>>(
        pf, rw, rb, rg, rbe, rm, rv, f1, out, 256);
}

// round 4
// speedup vs baseline: 1.9171x; 1.9171x over previous
#include <cuda_runtime.h>
#include <cstddef>

#define BN_EPS 1e-5f

// Scratch (device globals — no allocation allowed)
__device__ float g_q[4 * 64 * 4096];
__device__ float g_k[4 * 64 * 4096];
__device__ float g_v[4 * 64 * 4096];
__device__ float g_f[4 * 64 * 4096];

// ---------------------------------------------------------------------------
// 3x3 conv (pad=1) + folded BN + ReLU (+ optional residual add), NCHW, 64x64.
// grid: (16 pixel tiles of 16x16, cout_total/OC, B); block: 256 threads (1/px)
// Each thread accumulates OC output channels; ICB input channels per smem stage.
// ---------------------------------------------------------------------------
template <int CIN, int OC, int ICB, bool RESID>
__global__ void __launch_bounds__(256)
conv3x3_bn_relu(const float* __restrict__ in,
                const float* __restrict__ w,
                const float* __restrict__ cb,
                const float* __restrict__ cg,
                const float* __restrict__ cbe,
                const float* __restrict__ cm,
                const float* __restrict__ cv,
                const float* __restrict__ resid,
                float* __restrict__ out,
                int cout_total)
{
    const int tid    = threadIdx.x;
    const int tile   = blockIdx.x;
    const int ocbase = blockIdx.y * OC;
    const int b      = blockIdx.z;
    const int ty0 = (tile >> 2) * 16;
    const int tx0 = (tile & 3) * 16;
    const int px = tid & 15, py = tid >> 4;
    const int oy = ty0 + py, ox = tx0 + px;

    __shared__ float s_in[ICB * 324];        // ICB x 18 x 18
    __shared__ float s_w[OC * ICB * 12];     // rows padded to 12 for float4

    float acc[OC];
#pragma unroll
    for (int o = 0; o < OC; o++) acc[o] = 0.f;

    const float* ip0 = in + (((size_t)b * CIN) << 12);

    for (int ic0 = 0; ic0 < CIN; ic0 += ICB) {
        __syncthreads();
        // stage ICB input-channel tiles (18x18 with halo)
        for (int i = tid; i < ICB * 324; i += 256) {
            int icl = i / 324, rem = i - icl * 324;
            int r = rem / 18, c = rem - r * 18;
            int gy = ty0 - 1 + r, gx = tx0 - 1 + c;
            float v = 0.f;
            if ((unsigned)gy < 64u && (unsigned)gx < 64u)
                v = ip0[((size_t)(ic0 + icl) << 12) + (gy << 6) + gx];
            s_in[i] = v;
        }
        // stage weights for OC outputs x ICB inputs
        for (int i = tid; i < OC * ICB * 9; i += 256) {
            int o = i / (ICB * 9), rem = i - o * (ICB * 9);
            int icl = rem / 9, k = rem - icl * 9;
            s_w[(o * ICB + icl) * 12 + k] =
                w[((size_t)(ocbase + o) * CIN + ic0 + icl) * 9 + k];
        }
        __syncthreads();

#pragma unroll
        for (int icl = 0; icl < ICB; icl++) {
            float nb[9];
#pragma unroll
            for (int r = 0; r < 3; r++)
#pragma unroll
                for (int c = 0; c < 3; c++)
                    nb[r * 3 + c] = s_in[icl * 324 + (py + r) * 18 + px + c];

#pragma unroll
            for (int o = 0; o < OC; o++) {
                const float* wp = &s_w[(o * ICB + icl) * 12];
                const float4 w0 = *(const float4*)wp;
                const float4 w1 = *(const float4*)(wp + 4);
                const float  w8 = wp[8];
                float a = acc[o];
                a = fmaf(nb[0], w0.x, a);
                a = fmaf(nb[1], w0.y, a);
                a = fmaf(nb[2], w0.z, a);
                a = fmaf(nb[3], w0.w, a);
                a = fmaf(nb[4], w1.x, a);
                a = fmaf(nb[5], w1.y, a);
                a = fmaf(nb[6], w1.z, a);
                a = fmaf(nb[7], w1.w, a);
                a = fmaf(nb[8], w8,  a);
                acc[o] = a;
            }
        }
    }

#pragma unroll
    for (int o = 0; o < OC; o++) {
        int oc = ocbase + o;
        float inv = cg[oc] * rsqrtf(cv[oc] + BN_EPS);
        float bb  = fmaf(cb[oc], inv, cbe[oc] - cm[oc] * inv);
        float y   = fmaxf(fmaf(acc[o], inv, bb), 0.f);
        size_t gi = (((size_t)b * cout_total + oc) << 12) + (oy << 6) + ox;
        if (RESID) y += resid[gi];
        out[gi] = y;
    }
}

// ---------------------------------------------------------------------------
// Flash attention over q,k,v device buffers (layout [b][c][n], c=d=64, N=4096)
// grid: (64 n-tiles, 4 batches); block 256 threads (16x16, 4x4 fragments)
// Dynamic smem: Qs[64][64] + Ks[64][64] + Vs[64][68] + Ps[64][68] = 67584 B
// ---------------------------------------------------------------------------
__global__ void __launch_bounds__(256) attn_kernel()
{
    extern __shared__ float sm[];
    float* Qs = sm;                  // [d][n], stride 64
    float* Ks = Qs + 64 * 64;        // [d][m], stride 64
    float* Vs = Ks + 64 * 64;        // [m][c], stride 68 (padded)
    float* Ps = Vs + 64 * 68;        // [m][n], stride 68 (padded)

    const int tid = threadIdx.x;
    const int tx = tid & 15, ty = tid >> 4;
    const int tn = ty << 2, tm = tx << 2, tc = tx << 2;
    const int b  = blockIdx.y;
    const int n0 = blockIdx.x << 6;

    const float* qp = g_q + ((size_t)b << 18) + n0;
    const float* kp = g_k + ((size_t)b << 18);
    const float* vp = g_v + ((size_t)b << 18);

    for (int e = tid; e < 4096; e += 256)
        Qs[e] = qp[((e >> 6) << 12) + (e & 63)];

    float o[4][4];
    float mi[4], li[4];
#pragma unroll
    for (int i = 0; i < 4; i++) {
        mi[i] = -1e30f; li[i] = 0.f;
#pragma unroll
        for (int j = 0; j < 4; j++) o[i][j] = 0.f;
    }

    for (int t = 0; t < 64; t++) {
        __syncthreads();   // prev PV done before overwriting Ks/Vs; also covers Qs on t=0
        const int m0 = t << 6;
        for (int e = tid; e < 4096; e += 256) {
            int c = e >> 6, m = e & 63;
            float kv = kp[(c << 12) + m0 + m];
            float vv = vp[(c << 12) + m0 + m];
            Ks[e] = kv;              // [c][m]
            Vs[m * 68 + c] = vv;     // transposed
        }
        __syncthreads();

        // S = Q^T K (64x64 tile, 4x4 per thread)
        float s[4][4];
#pragma unroll
        for (int i = 0; i < 4; i++)
#pragma unroll
            for (int j = 0; j < 4; j++) s[i][j] = 0.f;

#pragma unroll 8
        for (int d = 0; d < 64; d++) {
            float4 qv = *(const float4*)&Qs[(d << 6) + tn];
            float4 kv = *(const float4*)&Ks[(d << 6) + tm];
            s[0][0] = fmaf(qv.x, kv.x, s[0][0]);
            s[0][1] = fmaf(qv.x, kv.y, s[0][1]);
            s[0][2] = fmaf(qv.x, kv.z, s[0][2]);
            s[0][3] = fmaf(qv.x, kv.w, s[0][3]);
            s[1][0] = fmaf(qv.y, kv.x, s[1][0]);
            s[1][1] = fmaf(qv.y, kv.y, s[1][1]);
            s[1][2] = fmaf(qv.y, kv.z, s[1][2]);
            s[1][3] = fmaf(qv.y, kv.w, s[1][3]);
            s[2][0] = fmaf(qv.z, kv.x, s[2][0]);
            s[2][1] = fmaf(qv.z, kv.y, s[2][1]);
            s[2][2] = fmaf(qv.z, kv.z, s[2][2]);
            s[2][3] = fmaf(qv.z, kv.w, s[2][3]);
            s[3][0] = fmaf(qv.w, kv.x, s[3][0]);
            s[3][1] = fmaf(qv.w, kv.y, s[3][1]);
            s[3][2] = fmaf(qv.w, kv.z, s[3][2]);
            s[3][3] = fmaf(qv.w, kv.w, s[3][3]);
        }

        // Online softmax. Rows tn..tn+3 are shared by the 16 lanes with equal ty;
        // lane = (ty&1)*16 + tx, so xor offsets 1,2,4,8 reduce within that group.
        float rmax[4];
#pragma unroll
        for (int i = 0; i < 4; i++)
            rmax[i] = fmaxf(fmaxf(s[i][0], s[i][1]), fmaxf(s[i][2], s[i][3]));
#pragma unroll
        for (int off = 8; off >= 1; off >>= 1)
#pragma unroll
            for (int i = 0; i < 4; i++)
                rmax[i] = fmaxf(rmax[i], __shfl_xor_sync(0xffffffffu, rmax[i], off));

        float corr[4], rsum[4];
#pragma unroll
        for (int i = 0; i < 4; i++) {
            float mn = fmaxf(mi[i], rmax[i]);
            corr[i] = __expf(mi[i] - mn);
            mi[i] = mn;
            rsum[i] = 0.f;
        }
#pragma unroll
        for (int i = 0; i < 4; i++)
#pragma unroll
            for (int j = 0; j < 4; j++) {
                float p = __expf(s[i][j] - mi[i]);
                s[i][j] = p;
                rsum[i] += p;
            }
#pragma unroll
        for (int off = 8; off >= 1; off >>= 1)
#pragma unroll
            for (int i = 0; i < 4; i++)
                rsum[i] += __shfl_xor_sync(0xffffffffu, rsum[i], off);
#pragma unroll
        for (int i = 0; i < 4; i++) {
            li[i] = li[i] * corr[i] + rsum[i];
#pragma unroll
            for (int j = 0; j < 4; j++) o[i][j] *= corr[i];
        }

        // Stage P as [m][n] for the PV GEMM
#pragma unroll
        for (int j = 0; j < 4; j++)
#pragma unroll
            for (int i = 0; i < 4; i++)
                Ps[(tm + j) * 68 + tn + i] = s[i][j];
        __syncthreads();

        // O += P V   (P[m][n] x V[m][c], both float4 rows)
#pragma unroll 8
        for (int m = 0; m < 64; m++) {
            float4 pv = *(const float4*)&Ps[m * 68 + tn];
            float4 vv = *(const float4*)&Vs[m * 68 + tc];
            o[0][0] = fmaf(pv.x, vv.x, o[0][0]);
            o[0][1] = fmaf(pv.x, vv.y, o[0][1]);
            o[0][2] = fmaf(pv.x, vv.z, o[0][2]);
            o[0][3] = fmaf(pv.x, vv.w, o[0][3]);
            o[1][0] = fmaf(pv.y, vv.x, o[1][0]);
            o[1][1] = fmaf(pv.y, vv.y, o[1][1]);
            o[1][2] = fmaf(pv.y, vv.z, o[1][2]);
            o[1][3] = fmaf(pv.y, vv.w, o[1][3]);
            o[2][0] = fmaf(pv.z, vv.x, o[2][0]);
            o[2][1] = fmaf(pv.z, vv.y, o[2][1]);
            o[2][2] = fmaf(pv.z, vv.z, o[2][2]);
            o[2][3] = fmaf(pv.z, vv.w, o[2][3]);
            o[3][0] = fmaf(pv.w, vv.x, o[3][0]);
            o[3][1] = fmaf(pv.w, vv.y, o[3][1]);
            o[3][2] = fmaf(pv.w, vv.z, o[3][2]);
            o[3][3] = fmaf(pv.w, vv.w, o[3][3]);
        }
    }

    // Normalize and write f[b][c][n]
#pragma unroll
    for (int i = 0; i < 4; i++) {
        float invl = 1.f / li[i];
#pragma unroll
        for (int j = 0; j < 4; j++)
            g_f[((size_t)(b * 64 + tc + j) << 12) + n0 + tn + i] = o[i][j] * invl;
    }
}

// ---------------------------------------------------------------------------
extern "C" void kernel_launch(void* const* d_in, const int* in_sizes, int n_in,
                              void* d_out, int out_size)
{
    (void)in_sizes; (void)n_in; (void)out_size;

    const float* f1  = (const float*)d_in[0];
    const float* f2  = (const float*)d_in[1];
    const float* qw  = (const float*)d_in[2];
    const float* qb  = (const float*)d_in[3];
    const float* qg  = (const float*)d_in[4];
    const float* qbe = (const float*)d_in[5];
    const float* qm  = (const float*)d_in[6];
    const float* qv  = (const float*)d_in[7];
    const float* kw  = (const float*)d_in[8];
    const float* kb  = (const float*)d_in[9];
    const float* kg  = (const float*)d_in[10];
    const float* kbe = (const float*)d_in[11];
    const float* km  = (const float*)d_in[12];
    const float* kv  = (const float*)d_in[13];
    const float* vw  = (const float*)d_in[14];
    const float* vb  = (const float*)d_in[15];
    const float* vg  = (const float*)d_in[16];
    const float* vbe = (const float*)d_in[17];
    const float* vm  = (const float*)d_in[18];
    const float* vv  = (const float*)d_in[19];
    const float* rw  = (const float*)d_in[20];
    const float* rb  = (const float*)d_in[21];
    const float* rg  = (const float*)d_in[22];
    const float* rbe = (const float*)d_in[23];
    const float* rm  = (const float*)d_in[24];
    const float* rv  = (const float*)d_in[25];
    float* out = (float*)d_out;

    float *pq, *pk, *pv, *pf;
    cudaGetSymbolAddress((void**)&pq, g_q);
    cudaGetSymbolAddress((void**)&pk, g_k);
    cudaGetSymbolAddress((void**)&pv, g_v);
    cudaGetSymbolAddress((void**)&pf, g_f);

    dim3 blk(256);
    // q = conv_bn_relu(feature2), k/v = conv_bn_relu(feature1)
    // OC=16 per block, grid.y=4 oc-groups -> 256 blocks per conv (full chip)
    conv3x3_bn_relu<256, 16, 8, false><<<dim3(16, 4, 4), blk>>>(
        f2, qw, qb, qg, qbe, qm, qv, nullptr, pq, 64);
    conv3x3_bn_relu<256, 16, 8, false><<<dim3(16, 4, 4), blk>>>(
        f1, kw, kb, kg, kbe, km, kv, nullptr, pk, 64);
    conv3x3_bn_relu<256, 16, 8, false><<<dim3(16, 4, 4), blk>>>(
        f1, vw, vb, vg, vbe, vm, vv, nullptr, pv, 64);

    const int attn_smem = (64 * 64 + 64 * 64 + 64 * 68 + 64 * 68) * (int)sizeof(float);
    cudaFuncSetAttribute(attn_kernel,
                         cudaFuncAttributeMaxDynamicSharedMemorySize, attn_smem);
    attn_kernel<<<dim3(64, 4), blk, attn_smem>>>();

    // out = feature1 + conv_bn_relu(f)  (256 oc -> 16 groups -> 1024 blocks)
    conv3x3_bn_relu<64, 16, 8, true><<<dim3(16, 16, 4), blk>>>(
        pf, rw, rb, rg, rbe, rm, rv, f1, out, 256);
}

// round 8
// speedup vs baseline: 2.5023x; 1.3052x over previous
#include <cuda_runtime.h>
#include <cuda_bf16.h>
#include <cstddef>
#include <cstdint>

#define BN_EPS 1e-5f

// ---------------------------------------------------------------------------
// Scratch (device globals — no allocation allowed)
// q,k: split bf16, layout [b][n][c] (rows of 64 bf16 = 128B)
// v:   split bf16, layout [b][c][n]
// f:   fp32 attention output [b][c][n]
// ---------------------------------------------------------------------------
__device__ unsigned short g_qh[4 * 4096 * 64];
__device__ unsigned short g_ql[4 * 4096 * 64];
__device__ unsigned short g_kh[4 * 4096 * 64];
__device__ unsigned short g_kl[4 * 4096 * 64];
__device__ unsigned short g_vh[4 * 64 * 4096];
__device__ unsigned short g_vl[4 * 64 * 4096];
__device__ float g_f[4 * 64 * 4096];

// ---------------------------------------------------------------------------
// PTX helpers (baseline sm_80+ features only — harness compiles via compute_103)
// ---------------------------------------------------------------------------
__device__ __forceinline__ uint32_t smem_u32(const void* p) {
    uint32_t a;
    asm("{ .reg .u64 t; cvta.to.shared.u64 t, %1; cvt.u32.u64 %0, t; }"
        : "=r"(a) : "l"(p));
    return a;
}

__device__ __forceinline__ void ldm_x2(uint32_t* r, uint32_t a) {
    asm volatile("ldmatrix.sync.aligned.m8n8.x2.shared.b16 {%0,%1}, [%2];"
                 : "=r"(r[0]), "=r"(r[1]) : "r"(a));
}
__device__ __forceinline__ void ldm_x4(uint32_t* r, uint32_t a) {
    asm volatile("ldmatrix.sync.aligned.m8n8.x4.shared.b16 {%0,%1,%2,%3}, [%4];"
                 : "=r"(r[0]), "=r"(r[1]), "=r"(r[2]), "=r"(r[3]) : "r"(a));
}
__device__ __forceinline__ void mma16816(float* d, const uint32_t* a, const uint32_t* b) {
    asm volatile("mma.sync.aligned.m16n8k16.row.col.f32.bf16.bf16.f32 "
                 "{%0,%1,%2,%3}, {%4,%5,%6,%7}, {%8,%9}, {%0,%1,%2,%3};"
                 : "+f"(d[0]), "+f"(d[1]), "+f"(d[2]), "+f"(d[3])
                 : "r"(a[0]), "r"(a[1]), "r"(a[2]), "r"(a[3]),
                   "r"(b[0]), "r"(b[1]));
}
// pack {lo16=bf16(plo), hi16=bf16(phi)}  (PTX: first src -> upper half)
__device__ __forceinline__ uint32_t pack_bf16x2(float lo, float hi) {
    uint32_t r;
    asm("cvt.rn.bf16x2.f32 %0, %1, %2;" : "=r"(r) : "f"(hi), "f"(lo));
    return r;
}

__device__ __forceinline__ void split_bf16(float y, unsigned short& h, unsigned short& l) {
    __nv_bfloat16 hb = __float2bfloat16(y);
    float r = y - __bfloat162float(hb);
    __nv_bfloat16 lb = __float2bfloat16(r);
    h = __bfloat16_as_ushort(hb);
    l = __bfloat16_as_ushort(lb);
}

// ---------------------------------------------------------------------------
// 3x3 conv (pad=1) + folded BN + ReLU, NCHW, 64x64 images.
// MODE 0: fp32 out [c][n] + residual add (final conv)
// MODE 1: split-bf16 out, layout [n][c]   (q, k)
// MODE 2: split-bf16 out, layout [c][n]   (v)
// ---------------------------------------------------------------------------
template <int CIN, int OC, int ICB, int MODE>
__global__ void __launch_bounds__(256)
conv3x3_bn_relu(const float* __restrict__ in,
                const float* __restrict__ w,
                const float* __restrict__ cb,
                const float* __restrict__ cg,
                const float* __restrict__ cbe,
                const float* __restrict__ cm,
                const float* __restrict__ cv,
                const float* __restrict__ resid,
                float* __restrict__ out32,
                unsigned short* __restrict__ outh,
                unsigned short* __restrict__ outl,
                int cout_total)
{
    const int tid    = threadIdx.x;
    const int tile   = blockIdx.x;
    const int ocbase = blockIdx.y * OC;
    const int b      = blockIdx.z;
    const int ty0 = (tile >> 2) * 16;
    const int tx0 = (tile & 3) * 16;
    const int px = tid & 15, py = tid >> 4;
    const int oy = ty0 + py, ox = tx0 + px;

    __shared__ float s_in[ICB * 324];
    __shared__ float s_w[OC * ICB * 12];

    float acc[OC];
#pragma unroll
    for (int o = 0; o < OC; o++) acc[o] = 0.f;

    const float* ip0 = in + (((size_t)b * CIN) << 12);

    for (int ic0 = 0; ic0 < CIN; ic0 += ICB) {
        __syncthreads();
        for (int i = tid; i < ICB * 324; i += 256) {
            int icl = i / 324, rem = i - icl * 324;
            int r = rem / 18, c = rem - r * 18;
            int gy = ty0 - 1 + r, gx = tx0 - 1 + c;
            float v = 0.f;
            if ((unsigned)gy < 64u && (unsigned)gx < 64u)
                v = ip0[((size_t)(ic0 + icl) << 12) + (gy << 6) + gx];
            s_in[i] = v;
        }
        for (int i = tid; i < OC * ICB * 9; i += 256) {
            int o = i / (ICB * 9), rem = i - o * (ICB * 9);
            int icl = rem / 9, k = rem - icl * 9;
            s_w[(o * ICB + icl) * 12 + k] =
                w[((size_t)(ocbase + o) * CIN + ic0 + icl) * 9 + k];
        }
        __syncthreads();

#pragma unroll
        for (int icl = 0; icl < ICB; icl++) {
            float nb[9];
#pragma unroll
            for (int r = 0; r < 3; r++)
#pragma unroll
                for (int c = 0; c < 3; c++)
                    nb[r * 3 + c] = s_in[icl * 324 + (py + r) * 18 + px + c];

#pragma unroll
            for (int o = 0; o < OC; o++) {
                const float* wp = &s_w[(o * ICB + icl) * 12];
                const float4 w0 = *(const float4*)wp;
                const float4 w1 = *(const float4*)(wp + 4);
                const float  w8 = wp[8];
                float a = acc[o];
                a = fmaf(nb[0], w0.x, a);
                a = fmaf(nb[1], w0.y, a);
                a = fmaf(nb[2], w0.z, a);
                a = fmaf(nb[3], w0.w, a);
                a = fmaf(nb[4], w1.x, a);
                a = fmaf(nb[5], w1.y, a);
                a = fmaf(nb[6], w1.z, a);
                a = fmaf(nb[7], w1.w, a);
                a = fmaf(nb[8], w8,  a);
                acc[o] = a;
            }
        }
    }

    float y[OC];
#pragma unroll
    for (int o = 0; o < OC; o++) {
        int oc = ocbase + o;
        float inv = cg[oc] * rsqrtf(cv[oc] + BN_EPS);
        float bb  = fmaf(cb[oc], inv, cbe[oc] - cm[oc] * inv);
        y[o] = fmaxf(fmaf(acc[o], inv, bb), 0.f);
    }

    const int n = (oy << 6) + ox;

    if (MODE == 0) {
#pragma unroll
        for (int o = 0; o < OC; o++) {
            size_t gi = (((size_t)b * cout_total + ocbase + o) << 12) + n;
            out32[gi] = y[o] + resid[gi];
        }
    } else if (MODE == 1) {
        size_t base = ((size_t)b * 4096 + n) * 64 + ocbase;
        uint32_t uh[OC / 2], ul[OC / 2];
#pragma unroll
        for (int j = 0; j < OC / 2; j++) {
            unsigned short h0, l0, h1, l1;
            split_bf16(y[2 * j], h0, l0);
            split_bf16(y[2 * j + 1], h1, l1);
            uh[j] = ((uint32_t)h1 << 16) | h0;
            ul[j] = ((uint32_t)l1 << 16) | l0;
        }
        uint4* ph = (uint4*)(outh + base);
        uint4* pl = (uint4*)(outl + base);
        ph[0] = make_uint4(uh[0], uh[1], uh[2], uh[3]);
        ph[1] = make_uint4(uh[4], uh[5], uh[6], uh[7]);
        pl[0] = make_uint4(ul[0], ul[1], ul[2], ul[3]);
        pl[1] = make_uint4(ul[4], ul[5], ul[6], ul[7]);
    } else {
#pragma unroll
        for (int o = 0; o < OC; o++) {
            size_t gi = (((size_t)(b * 64 + ocbase + o)) << 12) + n;
            unsigned short h, l;
            split_bf16(y[o], h, l);
            outh[gi] = h;
            outl[gi] = l;
        }
    }
}

// ---------------------------------------------------------------------------
// Flash attention with mma.sync bf16 (m16n8k16) + fp32 hi/lo splitting.
//   S  = Qh·Kh + Ql·Kh + Qh·Kl
//   PV = Ph·Vh + Pl·Vh + Ph·Vl
// grid (32 q-tiles of 128 rows, 4 batches), block 256 (8 warps x 16 rows).
// Smem rows padded to 72 bf16 (144B) -> conflict-free ldmatrix, no swizzle.
// All operands feed non-transposed ldmatrix:
//   S GEMM:  A = Q[n][c] rows, B = K[key][chan] rows
//   PV GEMM: A = P fragments (reg, == S accum layout), B = V[chan][key] rows
// ---------------------------------------------------------------------------
#define QS 72  // smem row stride (bf16 elems), 144 bytes

__global__ void __launch_bounds__(256) attn_mma_kernel()
{
    extern __shared__ unsigned short smu[];
    unsigned short* Qh = smu;            // 128 x QS
    unsigned short* Ql = smu + 9216;
    unsigned short* Kh = smu + 18432;    // 64 x QS  [key][chan]
    unsigned short* Kl = smu + 23040;
    unsigned short* Vh = smu + 27648;    // 64 x QS  [chan][key]
    unsigned short* Vl = smu + 32256;

    const int tid  = threadIdx.x;
    const int lane = tid & 31;
    const int warp = tid >> 5;
    const int gid  = lane >> 2, tg = lane & 3;
    const int b  = blockIdx.y;
    const int n0 = blockIdx.x << 7;
    const int mbase = warp << 4;

    // ---- load Q tile (128x64, hi/lo) into padded smem ----
    {
        int r = tid >> 1, h = (tid & 1) << 5;
        size_t src = ((size_t)(b * 4096 + n0 + r)) * 64 + h;
        const uint4* sh = (const uint4*)(g_qh + src);
        const uint4* sl = (const uint4*)(g_ql + src);
        uint4* dh = (uint4*)(Qh + r * QS + h);
        uint4* dl = (uint4*)(Ql + r * QS + h);
#pragma unroll
        for (int i = 0; i < 4; i++) { dh[i] = sh[i]; dl[i] = sl[i]; }
    }
    __syncthreads();

    // ---- Q fragments, resident for whole kernel (4 k-steps x 4 regs, hi/lo) ----
    uint32_t qfh[4][4], qfl[4][4];
    {
        uint32_t qhb = smem_u32(Qh), qlb = smem_u32(Ql);
        uint32_t ro = (uint32_t)(mbase + (lane & 15)) * (QS * 2) + ((lane >> 4) << 4);
#pragma unroll
        for (int i = 0; i < 4; i++) {
            ldm_x4(qfh[i], qhb + ro + i * 32);
            ldm_x4(qfl[i], qlb + ro + i * 32);
        }
    }

    const uint32_t khb = smem_u32(Kh), klb = smem_u32(Kl);
    const uint32_t vhb = smem_u32(Vh), vlb = smem_u32(Vl);
    const int l4 = lane & 15;
    const uint32_t bro = (uint32_t)(l4 & 7) * (QS * 2) + ((l4 >> 3) << 4);

    float O[8][4];
    float mi0 = -1e30f, mi1 = -1e30f, li0 = 0.f, li1 = 0.f;
#pragma unroll
    for (int j = 0; j < 8; j++)
#pragma unroll
        for (int k = 0; k < 4; k++) O[j][k] = 0.f;

    for (int t = 0; t < 64; t++) {
        __syncthreads();   // previous iteration's fragments consumed

        // ---- stage K (64x64 [key][chan]) and V (64x64 [chan][key]) hi/lo ----
        {
            int r = tid >> 2, s = (tid & 3) << 4;
            size_t kb = ((size_t)(b * 4096 + (t << 6) + r)) * 64 + s;
            const uint4* skh = (const uint4*)(g_kh + kb);
            const uint4* skl = (const uint4*)(g_kl + kb);
            uint4* dkh = (uint4*)(Kh + r * QS + s);
            uint4* dkl = (uint4*)(Kl + r * QS + s);
            dkh[0] = skh[0]; dkh[1] = skh[1];
            dkl[0] = skl[0]; dkl[1] = skl[1];
            size_t vb = (((size_t)(b * 64 + r)) << 12) + (t << 6) + s;
            const uint4* svh = (const uint4*)(g_vh + vb);
            const uint4* svl = (const uint4*)(g_vl + vb);
            uint4* dvh = (uint4*)(Vh + r * QS + s);
            uint4* dvl = (uint4*)(Vl + r * QS + s);
            dvh[0] = svh[0]; dvh[1] = svh[1];
            dvl[0] = svl[0]; dvl[1] = svl[1];
        }
        __syncthreads();

        // ---- S = Q K^T (16x64 per warp, 3 split passes) ----
        float sacc[8][4];
#pragma unroll
        for (int j = 0; j < 8; j++)
#pragma unroll
            for (int k = 0; k < 4; k++) sacc[j][k] = 0.f;

#pragma unroll
        for (int j = 0; j < 8; j++) {
#pragma unroll
            for (int i = 0; i < 4; i++) {
                uint32_t off = (uint32_t)(8 * j) * (QS * 2) + bro + i * 32;
                uint32_t bh[2], bl[2];
                ldm_x2(bh, khb + off);
                ldm_x2(bl, klb + off);
                mma16816(sacc[j], qfh[i], bh);
                mma16816(sacc[j], qfl[i], bh);
                mma16816(sacc[j], qfh[i], bl);
            }
        }

        // ---- online softmax (rows mbase+gid, mbase+gid+8) ----
        float rm0 = -1e30f, rm1 = -1e30f;
#pragma unroll
        for (int j = 0; j < 8; j++) {
            rm0 = fmaxf(rm0, fmaxf(sacc[j][0], sacc[j][1]));
            rm1 = fmaxf(rm1, fmaxf(sacc[j][2], sacc[j][3]));
        }
        rm0 = fmaxf(rm0, __shfl_xor_sync(0xffffffffu, rm0, 1));
        rm0 = fmaxf(rm0, __shfl_xor_sync(0xffffffffu, rm0, 2));
        rm1 = fmaxf(rm1, __shfl_xor_sync(0xffffffffu, rm1, 1));
        rm1 = fmaxf(rm1, __shfl_xor_sync(0xffffffffu, rm1, 2));

        float mn0 = fmaxf(mi0, rm0), mn1 = fmaxf(mi1, rm1);
        float c0 = __expf(mi0 - mn0), c1 = __expf(mi1 - mn1);
        mi0 = mn0; mi1 = mn1;

        float rs0 = 0.f, rs1 = 0.f;
        uint32_t ph[16], pl[16];
#pragma unroll
        for (int j = 0; j < 8; j++) {
            float p00 = __expf(sacc[j][0] - mi0);
            float p01 = __expf(sacc[j][1] - mi0);
            float p10 = __expf(sacc[j][2] - mi1);
            float p11 = __expf(sacc[j][3] - mi1);
            rs0 += p00 + p01;
            rs1 += p10 + p11;
            uint32_t h0 = pack_bf16x2(p00, p01);
            uint32_t h1 = pack_bf16x2(p10, p11);
            ph[2 * j]     = h0;
            ph[2 * j + 1] = h1;
            float r00 = p00 - __uint_as_float(h0 << 16);
            float r01 = p01 - __uint_as_float(h0 & 0xffff0000u);
            float r10 = p10 - __uint_as_float(h1 << 16);
            float r11 = p11 - __uint_as_float(h1 & 0xffff0000u);
            pl[2 * j]     = pack_bf16x2(r00, r01);
            pl[2 * j + 1] = pack_bf16x2(r10, r11);
        }
        rs0 += __shfl_xor_sync(0xffffffffu, rs0, 1);
        rs0 += __shfl_xor_sync(0xffffffffu, rs0, 2);
        rs1 += __shfl_xor_sync(0xffffffffu, rs1, 1);
        rs1 += __shfl_xor_sync(0xffffffffu, rs1, 2);
        li0 = li0 * c0 + rs0;
        li1 = li1 * c1 + rs1;

#pragma unroll
        for (int j = 0; j < 8; j++) {
            O[j][0] *= c0; O[j][1] *= c0;
            O[j][2] *= c1; O[j][3] *= c1;
        }

        // ---- O += P V (P fragments == S accum layout; V [chan][key] rows) ----
#pragma unroll
        for (int j = 0; j < 8; j++) {
#pragma unroll
            for (int i = 0; i < 4; i++) {
                uint32_t off = (uint32_t)(8 * j) * (QS * 2) + bro + i * 32;
                uint32_t bvh[2], bvl[2];
                ldm_x2(bvh, vhb + off);
                ldm_x2(bvl, vlb + off);
                mma16816(O[j], &ph[4 * i], bvh);
                mma16816(O[j], &pl[4 * i], bvh);
                mma16816(O[j], &ph[4 * i], bvl);
            }
        }
    }

    // ---- normalize, write f[b][c][n] ----
    {
        float i0 = 1.f / li0, i1 = 1.f / li1;
        int r0 = n0 + mbase + gid, r1 = r0 + 8;
#pragma unroll
        for (int j = 0; j < 8; j++) {
            int c = 8 * j + 2 * tg;
            g_f[(((size_t)(b * 64 + c))     << 12) + r0] = O[j][0] * i0;
            g_f[(((size_t)(b * 64 + c + 1)) << 12) + r0] = O[j][1] * i0;
            g_f[(((size_t)(b * 64 + c))     << 12) + r1] = O[j][2] * i1;
            g_f[(((size_t)(b * 64 + c + 1)) << 12) + r1] = O[j][3] * i1;
        }
    }
}

// ---------------------------------------------------------------------------
extern "C" void kernel_launch(void* const* d_in, const int* in_sizes, int n_in,
                              void* d_out, int out_size)
{
    (void)in_sizes; (void)n_in; (void)out_size;

    const float* f1  = (const float*)d_in[0];
    const float* f2  = (const float*)d_in[1];
    const float* qw  = (const float*)d_in[2];
    const float* qb  = (const float*)d_in[3];
    const float* qg  = (const float*)d_in[4];
    const float* qbe = (const float*)d_in[5];
    const float* qm  = (const float*)d_in[6];
    const float* qv  = (const float*)d_in[7];
    const float* kw  = (const float*)d_in[8];
    const float* kb  = (const float*)d_in[9];
    const float* kg  = (const float*)d_in[10];
    const float* kbe = (const float*)d_in[11];
    const float* km  = (const float*)d_in[12];
    const float* kv  = (const float*)d_in[13];
    const float* vw  = (const float*)d_in[14];
    const float* vb  = (const float*)d_in[15];
    const float* vg  = (const float*)d_in[16];
    const float* vbe = (const float*)d_in[17];
    const float* vm  = (const float*)d_in[18];
    const float* vv  = (const float*)d_in[19];
    const float* rw  = (const float*)d_in[20];
    const float* rb  = (const float*)d_in[21];
    const float* rg  = (const float*)d_in[22];
    const float* rbe = (const float*)d_in[23];
    const float* rm  = (const float*)d_in[24];
    const float* rv  = (const float*)d_in[25];
    float* out = (float*)d_out;

    unsigned short *pqh, *pql, *pkh, *pkl, *pvh, *pvl;
    float* pf;
    cudaGetSymbolAddress((void**)&pqh, g_qh);
    cudaGetSymbolAddress((void**)&pql, g_ql);
    cudaGetSymbolAddress((void**)&pkh, g_kh);
    cudaGetSymbolAddress((void**)&pkl, g_kl);
    cudaGetSymbolAddress((void**)&pvh, g_vh);
    cudaGetSymbolAddress((void**)&pvl, g_vl);
    cudaGetSymbolAddress((void**)&pf, g_f);

    dim3 blk(256);
    // q = conv(feature2) -> split bf16 [n][c]; k = conv(feature1) -> [n][c]
    conv3x3_bn_relu<256, 16, 8, 1><<<dim3(16, 4, 4), blk>>>(
        f2, qw, qb, qg, qbe, qm, qv, nullptr, nullptr, pqh, pql, 64);
    conv3x3_bn_relu<256, 16, 8, 1><<<dim3(16, 4, 4), blk>>>(
        f1, kw, kb, kg, kbe, km, kv, nullptr, nullptr, pkh, pkl, 64);
    // v = conv(feature1) -> split bf16 [c][n]
    conv3x3_bn_relu<256, 16, 8, 2><<<dim3(16, 4, 4), blk>>>(
        f1, vw, vb, vg, vbe, vm, vv, nullptr, nullptr, pvh, pvl, 64);

    const int attn_smem = 36864 * (int)sizeof(unsigned short);  // 73728 B
    cudaFuncSetAttribute(attn_mma_kernel,
                         cudaFuncAttributeMaxDynamicSharedMemorySize, attn_smem);
    attn_mma_kernel<<<dim3(32, 4), blk, attn_smem>>>();

    // out = feature1 + conv_bn_relu(f)
    conv3x3_bn_relu<64, 16, 8, 0><<<dim3(16, 16, 4), blk>>>(
        pf, rw, rb, rg, rbe, rm, rv, f1, out, nullptr, nullptr, 256);
}

// round 11
// speedup vs baseline: 3.3157x; 1.3251x over previous
#include <cuda_runtime.h>
#include <cuda_bf16.h>
#include <cstddef>
#include <cstdint>

#define BN_EPS 1e-5f

// ---------------------------------------------------------------------------
// Scratch (device globals — no allocation allowed)
// q,k: split bf16, layout [b][n][c] (rows of 64 bf16 = 128B)
// v:   split bf16, layout [b][c][n]
// f:   fp32 attention output [b][c][n]
// ---------------------------------------------------------------------------
__device__ unsigned short g_qh[4 * 4096 * 64];
__device__ unsigned short g_ql[4 * 4096 * 64];
__device__ unsigned short g_kh[4 * 4096 * 64];
__device__ unsigned short g_kl[4 * 4096 * 64];
__device__ unsigned short g_vh[4 * 64 * 4096];
__device__ unsigned short g_vl[4 * 64 * 4096];
__device__ float g_f[4 * 64 * 4096];

// ---------------------------------------------------------------------------
// PTX helpers (baseline sm_80+ features only — harness compiles via compute_103)
// ---------------------------------------------------------------------------
__device__ __forceinline__ uint32_t smem_u32(const void* p) {
    uint32_t a;
    asm("{ .reg .u64 t; cvta.to.shared.u64 t, %1; cvt.u32.u64 %0, t; }"
        : "=r"(a) : "l"(p));
    return a;
}

__device__ __forceinline__ void ldm_x2(uint32_t* r, uint32_t a) {
    asm volatile("ldmatrix.sync.aligned.m8n8.x2.shared.b16 {%0,%1}, [%2];"
                 : "=r"(r[0]), "=r"(r[1]) : "r"(a));
}
__device__ __forceinline__ void ldm_x4(uint32_t* r, uint32_t a) {
    asm volatile("ldmatrix.sync.aligned.m8n8.x4.shared.b16 {%0,%1,%2,%3}, [%4];"
                 : "=r"(r[0]), "=r"(r[1]), "=r"(r[2]), "=r"(r[3]) : "r"(a));
}
__device__ __forceinline__ void mma16816(float* d, const uint32_t* a, const uint32_t* b) {
    asm volatile("mma.sync.aligned.m16n8k16.row.col.f32.bf16.bf16.f32 "
                 "{%0,%1,%2,%3}, {%4,%5,%6,%7}, {%8,%9}, {%0,%1,%2,%3};"
                 : "+f"(d[0]), "+f"(d[1]), "+f"(d[2]), "+f"(d[3])
                 : "r"(a[0]), "r"(a[1]), "r"(a[2]), "r"(a[3]),
                   "r"(b[0]), "r"(b[1]));
}
// pack {lo16=bf16(plo), hi16=bf16(phi)}  (PTX: first src -> upper half)
__device__ __forceinline__ uint32_t pack_bf16x2(float lo, float hi) {
    uint32_t r;
    asm("cvt.rn.bf16x2.f32 %0, %1, %2;" : "=r"(r) : "f"(hi), "f"(lo));
    return r;
}

__device__ __forceinline__ void split_bf16(float y, unsigned short& h, unsigned short& l) {
    __nv_bfloat16 hb = __float2bfloat16(y);
    float r = y - __bfloat162float(hb);
    __nv_bfloat16 lb = __float2bfloat16(r);
    h = __bfloat16_as_ushort(hb);
    l = __bfloat16_as_ushort(lb);
}

// ---------------------------------------------------------------------------
// 3x3 conv (pad=1) + folded BN + ReLU as implicit GEMM on tensor cores.
// Decomposition: 9 shifted GEMMs, K-chunks of 16 input channels.
//   A (m) = pixels: shifted halo-tile rows [pixel][ic]  (stride 40 elems = 80B)
//   B (n) = 64 out channels: weights [off][oc][ic]      (stride 24 elems = 48B)
// Inputs (fp32 [c][n] NCHW) and weights are hi/lo-split to bf16 during staging;
// 3-pass mma (AhBh + AlBh + AhBl) recovers ~fp32 accuracy.
// Block: 256 thr (8 warps x 16 pixels), tile = 128 pixels (2 image rows) x 64 oc.
// grid (32 pixel tiles, oc_groups, B).
// MODE 0: fp32 out [c][n] + residual add (final conv)
// MODE 1: split-bf16 out [n][c] (q, k)     MODE 2: split-bf16 out [c][n] (v)
// ---------------------------------------------------------------------------
#define XTILE 10560   // 4*66 pixel rows * 40 elems
#define WTILE 13824   // 9*64 rows * 24 elems
#define CONV_SMEM (2 * (XTILE + WTILE) * 2 + 512)

template <int CIN, int MODE>
__global__ void __launch_bounds__(256)
conv3x3_mma(const float* __restrict__ in,
            const float* __restrict__ w,
            const float* __restrict__ cb,
            const float* __restrict__ cg,
            const float* __restrict__ cbe,
            const float* __restrict__ cm,
            const float* __restrict__ cv,
            const float* __restrict__ resid,
            float* __restrict__ out32,
            unsigned short* __restrict__ outh,
            unsigned short* __restrict__ outl,
            int cout_total)
{
    extern __shared__ unsigned short smu[];
    unsigned short* XH = smu;
    unsigned short* XL = XH + XTILE;
    unsigned short* WH = XL + XTILE;
    unsigned short* WL = WH + WTILE;
    float* BN = (float*)(WL + WTILE);   // [64][2]: inv, bias

    const int tid  = threadIdx.x;
    const int lane = tid & 31;
    const int warp = tid >> 5;
    const int l4   = lane & 15;
    const int ocb  = blockIdx.y << 6;
    const int b    = blockIdx.z;
    const int r0   = blockIdx.x << 1;    // first image row of tile
    const int n0   = blockIdx.x << 7;    // first pixel of tile
    const int y    = warp >> 2;          // local image row (0/1)
    const int xb   = (warp & 3) << 4;    // x base of warp's 16 pixels

    if (tid < 64) {
        int oc = ocb + tid;
        float inv = cg[oc] * rsqrtf(cv[oc] + BN_EPS);
        BN[tid * 2]     = inv;
        BN[tid * 2 + 1] = fmaf(cb[oc], inv, cbe[oc] - cm[oc] * inv);
    }

    float acc[8][4];
#pragma unroll
    for (int nc = 0; nc < 8; nc++)
#pragma unroll
        for (int k = 0; k < 4; k++) acc[nc][k] = 0.f;

    const uint32_t xhb = smem_u32(XH), xlb = smem_u32(XL);
    const uint32_t whb = smem_u32(WH), wlb = smem_u32(WL);

    for (int ic0 = 0; ic0 < CIN; ic0 += 16) {
        __syncthreads();
        // ---- stage input halo tile (4 rows x 66 cols x 16 ic), split h/l ----
        for (int i = tid; i < 4224; i += 256) {
            int icl = i / 264, rem = i - icl * 264;
            int hy = rem / 66, hx = rem - hy * 66;
            int gy = r0 - 1 + hy, gx = hx - 1;
            float v = 0.f;
            if ((unsigned)gy < 64u && (unsigned)gx < 64u)
                v = in[(((size_t)(b * CIN + ic0 + icl)) << 12) + (gy << 6) + gx];
            unsigned short h, l;
            split_bf16(v, h, l);
            int si = (hy * 66 + hx) * 40 + icl;
            XH[si] = h; XL[si] = l;
        }
        // ---- stage weights for all 9 taps (64 oc x 16 ic), split h/l ----
        for (int i = tid; i < 9216; i += 256) {
            int oc = i / 144, r = i - oc * 144;
            int icl = r / 9, off = r - icl * 9;
            float v = w[((size_t)(ocb + oc) * CIN + ic0 + icl) * 9 + off];
            unsigned short h, l;
            split_bf16(v, h, l);
            int si = (off * 64 + oc) * 24 + icl;
            WH[si] = h; WL[si] = l;
        }
        __syncthreads();

#pragma unroll
        for (int ky = 0; ky < 3; ky++) {
#pragma unroll
            for (int kx = 0; kx < 3; kx++) {
                // A: 16 shifted pixel rows x 16 ic (same recipe as attn Q frags)
                uint32_t aro = (uint32_t)((y + ky) * 66 + xb + l4 + kx) * 80 +
                               ((lane >> 4) << 4);
                uint32_t afh[4], afl[4];
                ldm_x4(afh, xhb + aro);
                ldm_x4(afl, xlb + aro);

                uint32_t bro = (uint32_t)((ky * 3 + kx) * 64 + l4) * 48 +
                               ((lane >> 4) << 4);
#pragma unroll
                for (int g = 0; g < 4; g++) {
                    uint32_t bh[4], bl[4];
                    ldm_x4(bh, whb + bro + g * 768);
                    ldm_x4(bl, wlb + bro + g * 768);
                    // x4 over 16 oc rows: frag(oc 0-7) = {r0,r2}, frag(oc 8-15) = {r1,r3}
                    uint32_t b0h[2] = {bh[0], bh[2]}, b1h[2] = {bh[1], bh[3]};
                    uint32_t b0l[2] = {bl[0], bl[2]}, b1l[2] = {bl[1], bl[3]};
                    mma16816(acc[2 * g],     afh, b0h);
                    mma16816(acc[2 * g],     afl, b0h);
                    mma16816(acc[2 * g],     afh, b0l);
                    mma16816(acc[2 * g + 1], afh, b1h);
                    mma16816(acc[2 * g + 1], afl, b1h);
                    mma16816(acc[2 * g + 1], afh, b1l);
                }
            }
        }
    }

    // ---- BN + ReLU epilogue; D rows = pixels, cols = oc ----
    const int gid = lane >> 2, tg = lane & 3;
    const int p0 = n0 + (warp << 4) + gid;   // pixel of acc rows [0],[1]
    const int p1 = p0 + 8;                   // pixel of acc rows [2],[3]

#pragma unroll
    for (int nc = 0; nc < 8; nc++) {
        int c0 = nc * 8 + tg * 2;
        float i0 = BN[c0 * 2],     b0 = BN[c0 * 2 + 1];
        float i1 = BN[c0 * 2 + 2], b1 = BN[c0 * 2 + 3];
        float y00 = fmaxf(fmaf(acc[nc][0], i0, b0), 0.f);
        float y01 = fmaxf(fmaf(acc[nc][1], i1, b1), 0.f);
        float y10 = fmaxf(fmaf(acc[nc][2], i0, b0), 0.f);
        float y11 = fmaxf(fmaf(acc[nc][3], i1, b1), 0.f);

        if (MODE == 0) {
            size_t ga = (((size_t)(b * cout_total + ocb + c0)) << 12);
            size_t gb = ga + 4096;
            out32[ga + p0] = y00 + resid[ga + p0];
            out32[gb + p0] = y01 + resid[gb + p0];
            out32[ga + p1] = y10 + resid[ga + p1];
            out32[gb + p1] = y11 + resid[gb + p1];
        } else if (MODE == 1) {
            unsigned short h00, l00, h01, l01, h10, l10, h11, l11;
            split_bf16(y00, h00, l00); split_bf16(y01, h01, l01);
            split_bf16(y10, h10, l10); split_bf16(y11, h11, l11);
            size_t a0 = ((size_t)(b * 4096 + p0)) * 64 + c0;
            size_t a1 = ((size_t)(b * 4096 + p1)) * 64 + c0;
            *(uint32_t*)(outh + a0) = ((uint32_t)h01 << 16) | h00;
            *(uint32_t*)(outl + a0) = ((uint32_t)l01 << 16) | l00;
            *(uint32_t*)(outh + a1) = ((uint32_t)h11 << 16) | h10;
            *(uint32_t*)(outl + a1) = ((uint32_t)l11 << 16) | l10;
        } else {
            unsigned short h, l;
            size_t ga = (((size_t)(b * 64 + c0)) << 12);
            size_t gb = ga + 4096;
            split_bf16(y00, h, l); outh[ga + p0] = h; outl[ga + p0] = l;
            split_bf16(y01, h, l); outh[gb + p0] = h; outl[gb + p0] = l;
            split_bf16(y10, h, l); outh[ga + p1] = h; outl[ga + p1] = l;
            split_bf16(y11, h, l); outh[gb + p1] = h; outl[gb + p1] = l;
        }
    }
}

// ---------------------------------------------------------------------------
// Flash attention with mma.sync bf16 (m16n8k16) + fp32 hi/lo splitting.
// (unchanged from R8 — verified at 200us, tensor pipe active)
// ---------------------------------------------------------------------------
#define QS 72  // smem row stride (bf16 elems), 144 bytes

__global__ void __launch_bounds__(256) attn_mma_kernel()
{
    extern __shared__ unsigned short smu[];
    unsigned short* Qh = smu;            // 128 x QS
    unsigned short* Ql = smu + 9216;
    unsigned short* Kh = smu + 18432;    // 64 x QS  [key][chan]
    unsigned short* Kl = smu + 23040;
    unsigned short* Vh = smu + 27648;    // 64 x QS  [chan][key]
    unsigned short* Vl = smu + 32256;

    const int tid  = threadIdx.x;
    const int lane = tid & 31;
    const int warp = tid >> 5;
    const int gid  = lane >> 2, tg = lane & 3;
    const int b  = blockIdx.y;
    const int n0 = blockIdx.x << 7;
    const int mbase = warp << 4;

    // ---- load Q tile (128x64, hi/lo) into padded smem ----
    {
        int r = tid >> 1, h = (tid & 1) << 5;
        size_t src = ((size_t)(b * 4096 + n0 + r)) * 64 + h;
        const uint4* sh = (const uint4*)(g_qh + src);
        const uint4* sl = (const uint4*)(g_ql + src);
        uint4* dh = (uint4*)(Qh + r * QS + h);
        uint4* dl = (uint4*)(Ql + r * QS + h);
#pragma unroll
        for (int i = 0; i < 4; i++) { dh[i] = sh[i]; dl[i] = sl[i]; }
    }
    __syncthreads();

    // ---- Q fragments, resident for whole kernel ----
    uint32_t qfh[4][4], qfl[4][4];
    {
        uint32_t qhb = smem_u32(Qh), qlb = smem_u32(Ql);
        uint32_t ro = (uint32_t)(mbase + (lane & 15)) * (QS * 2) + ((lane >> 4) << 4);
#pragma unroll
        for (int i = 0; i < 4; i++) {
            ldm_x4(qfh[i], qhb + ro + i * 32);
            ldm_x4(qfl[i], qlb + ro + i * 32);
        }
    }

    const uint32_t khb = smem_u32(Kh), klb = smem_u32(Kl);
    const uint32_t vhb = smem_u32(Vh), vlb = smem_u32(Vl);
    const int l4 = lane & 15;
    const uint32_t bro = (uint32_t)(l4 & 7) * (QS * 2) + ((l4 >> 3) << 4);

    float O[8][4];
    float mi0 = -1e30f, mi1 = -1e30f, li0 = 0.f, li1 = 0.f;
#pragma unroll
    for (int j = 0; j < 8; j++)
#pragma unroll
        for (int k = 0; k < 4; k++) O[j][k] = 0.f;

    for (int t = 0; t < 64; t++) {
        __syncthreads();

        {
            int r = tid >> 2, s = (tid & 3) << 4;
            size_t kb = ((size_t)(b * 4096 + (t << 6) + r)) * 64 + s;
            const uint4* skh = (const uint4*)(g_kh + kb);
            const uint4* skl = (const uint4*)(g_kl + kb);
            uint4* dkh = (uint4*)(Kh + r * QS + s);
            uint4* dkl = (uint4*)(Kl + r * QS + s);
            dkh[0] = skh[0]; dkh[1] = skh[1];
            dkl[0] = skl[0]; dkl[1] = skl[1];
            size_t vb = (((size_t)(b * 64 + r)) << 12) + (t << 6) + s;
            const uint4* svh = (const uint4*)(g_vh + vb);
            const uint4* svl = (const uint4*)(g_vl + vb);
            uint4* dvh = (uint4*)(Vh + r * QS + s);
            uint4* dvl = (uint4*)(Vl + r * QS + s);
            dvh[0] = svh[0]; dvh[1] = svh[1];
            dvl[0] = svl[0]; dvl[1] = svl[1];
        }
        __syncthreads();

        float sacc[8][4];
#pragma unroll
        for (int j = 0; j < 8; j++)
#pragma unroll
            for (int k = 0; k < 4; k++) sacc[j][k] = 0.f;

#pragma unroll
        for (int j = 0; j < 8; j++) {
#pragma unroll
            for (int i = 0; i < 4; i++) {
                uint32_t off = (uint32_t)(8 * j) * (QS * 2) + bro + i * 32;
                uint32_t bh[2], bl[2];
                ldm_x2(bh, khb + off);
                ldm_x2(bl, klb + off);
                mma16816(sacc[j], qfh[i], bh);
                mma16816(sacc[j], qfl[i], bh);
                mma16816(sacc[j], qfh[i], bl);
            }
        }

        float rm0 = -1e30f, rm1 = -1e30f;
#pragma unroll
        for (int j = 0; j < 8; j++) {
            rm0 = fmaxf(rm0, fmaxf(sacc[j][0], sacc[j][1]));
            rm1 = fmaxf(rm1, fmaxf(sacc[j][2], sacc[j][3]));
        }
        rm0 = fmaxf(rm0, __shfl_xor_sync(0xffffffffu, rm0, 1));
        rm0 = fmaxf(rm0, __shfl_xor_sync(0xffffffffu, rm0, 2));
        rm1 = fmaxf(rm1, __shfl_xor_sync(0xffffffffu, rm1, 1));
        rm1 = fmaxf(rm1, __shfl_xor_sync(0xffffffffu, rm1, 2));

        float mn0 = fmaxf(mi0, rm0), mn1 = fmaxf(mi1, rm1);
        float c0 = __expf(mi0 - mn0), c1 = __expf(mi1 - mn1);
        mi0 = mn0; mi1 = mn1;

        float rs0 = 0.f, rs1 = 0.f;
        uint32_t ph[16], pl[16];
#pragma unroll
        for (int j = 0; j < 8; j++) {
            float p00 = __expf(sacc[j][0] - mi0);
            float p01 = __expf(sacc[j][1] - mi0);
            float p10 = __expf(sacc[j][2] - mi1);
            float p11 = __expf(sacc[j][3] - mi1);
            rs0 += p00 + p01;
            rs1 += p10 + p11;
            uint32_t h0 = pack_bf16x2(p00, p01);
            uint32_t h1 = pack_bf16x2(p10, p11);
            ph[2 * j]     = h0;
            ph[2 * j + 1] = h1;
            float r00 = p00 - __uint_as_float(h0 << 16);
            float r01 = p01 - __uint_as_float(h0 & 0xffff0000u);
            float r10 = p10 - __uint_as_float(h1 << 16);
            float r11 = p11 - __uint_as_float(h1 & 0xffff0000u);
            pl[2 * j]     = pack_bf16x2(r00, r01);
            pl[2 * j + 1] = pack_bf16x2(r10, r11);
        }
        rs0 += __shfl_xor_sync(0xffffffffu, rs0, 1);
        rs0 += __shfl_xor_sync(0xffffffffu, rs0, 2);
        rs1 += __shfl_xor_sync(0xffffffffu, rs1, 1);
        rs1 += __shfl_xor_sync(0xffffffffu, rs1, 2);
        li0 = li0 * c0 + rs0;
        li1 = li1 * c1 + rs1;

#pragma unroll
        for (int j = 0; j < 8; j++) {
            O[j][0] *= c0; O[j][1] *= c0;
            O[j][2] *= c1; O[j][3] *= c1;
        }

#pragma unroll
        for (int j = 0; j < 8; j++) {
#pragma unroll
            for (int i = 0; i < 4; i++) {
                uint32_t off = (uint32_t)(8 * j) * (QS * 2) + bro + i * 32;
                uint32_t bvh[2], bvl[2];
                ldm_x2(bvh, vhb + off);
                ldm_x2(bvl, vlb + off);
                mma16816(O[j], &ph[4 * i], bvh);
                mma16816(O[j], &pl[4 * i], bvh);
                mma16816(O[j], &ph[4 * i], bvl);
            }
        }
    }

    // ---- normalize, write f[b][c][n] ----
    {
        float i0 = 1.f / li0, i1 = 1.f / li1;
        int r0 = n0 + mbase + gid, r1 = r0 + 8;
#pragma unroll
        for (int j = 0; j < 8; j++) {
            int c = 8 * j + 2 * tg;
            g_f[(((size_t)(b * 64 + c))     << 12) + r0] = O[j][0] * i0;
            g_f[(((size_t)(b * 64 + c + 1)) << 12) + r0] = O[j][1] * i0;
            g_f[(((size_t)(b * 64 + c))     << 12) + r1] = O[j][2] * i1;
            g_f[(((size_t)(b * 64 + c + 1)) << 12) + r1] = O[j][3] * i1;
        }
    }
}

// ---------------------------------------------------------------------------
extern "C" void kernel_launch(void* const* d_in, const int* in_sizes, int n_in,
                              void* d_out, int out_size)
{
    (void)in_sizes; (void)n_in; (void)out_size;

    const float* f1  = (const float*)d_in[0];
    const float* f2  = (const float*)d_in[1];
    const float* qw  = (const float*)d_in[2];
    const float* qb  = (const float*)d_in[3];
    const float* qg  = (const float*)d_in[4];
    const float* qbe = (const float*)d_in[5];
    const float* qm  = (const float*)d_in[6];
    const float* qv  = (const float*)d_in[7];
    const float* kw  = (const float*)d_in[8];
    const float* kb  = (const float*)d_in[9];
    const float* kg  = (const float*)d_in[10];
    const float* kbe = (const float*)d_in[11];
    const float* km  = (const float*)d_in[12];
    const float* kv  = (const float*)d_in[13];
    const float* vw  = (const float*)d_in[14];
    const float* vb  = (const float*)d_in[15];
    const float* vg  = (const float*)d_in[16];
    const float* vbe = (const float*)d_in[17];
    const float* vm  = (const float*)d_in[18];
    const float* vv  = (const float*)d_in[19];
    const float* rw  = (const float*)d_in[20];
    const float* rb  = (const float*)d_in[21];
    const float* rg  = (const float*)d_in[22];
    const float* rbe = (const float*)d_in[23];
    const float* rm  = (const float*)d_in[24];
    const float* rv  = (const float*)d_in[25];
    float* out = (float*)d_out;

    unsigned short *pqh, *pql, *pkh, *pkl, *pvh, *pvl;
    float* pf;
    cudaGetSymbolAddress((void**)&pqh, g_qh);
    cudaGetSymbolAddress((void**)&pql, g_ql);
    cudaGetSymbolAddress((void**)&pkh, g_kh);
    cudaGetSymbolAddress((void**)&pkl, g_kl);
    cudaGetSymbolAddress((void**)&pvh, g_vh);
    cudaGetSymbolAddress((void**)&pvl, g_vl);
    cudaGetSymbolAddress((void**)&pf, g_f);

    cudaFuncSetAttribute(conv3x3_mma<256, 1>,
                         cudaFuncAttributeMaxDynamicSharedMemorySize, CONV_SMEM);
    cudaFuncSetAttribute(conv3x3_mma<256, 2>,
                         cudaFuncAttributeMaxDynamicSharedMemorySize, CONV_SMEM);
    cudaFuncSetAttribute(conv3x3_mma<64, 0>,
                         cudaFuncAttributeMaxDynamicSharedMemorySize, CONV_SMEM);

    dim3 blk(256);
    // q = conv(feature2) -> split bf16 [n][c]; k = conv(feature1) -> [n][c]
    conv3x3_mma<256, 1><<<dim3(32, 1, 4), blk, CONV_SMEM>>>(
        f2, qw, qb, qg, qbe, qm, qv, nullptr, nullptr, pqh, pql, 64);
    conv3x3_mma<256, 1><<<dim3(32, 1, 4), blk, CONV_SMEM>>>(
        f1, kw, kb, kg, kbe, km, kv, nullptr, nullptr, pkh, pkl, 64);
    // v = conv(feature1) -> split bf16 [c][n]
    conv3x3_mma<256, 2><<<dim3(32, 1, 4), blk, CONV_SMEM>>>(
        f1, vw, vb, vg, vbe, vm, vv, nullptr, nullptr, pvh, pvl, 64);

    const int attn_smem = 36864 * (int)sizeof(unsigned short);  // 73728 B
    cudaFuncSetAttribute(attn_mma_kernel,
                         cudaFuncAttributeMaxDynamicSharedMemorySize, attn_smem);
    attn_mma_kernel<<<dim3(32, 4), blk, attn_smem>>>();

    // out = feature1 + conv_bn_relu(f)
    conv3x3_mma<64, 0><<<dim3(32, 4, 4), blk, CONV_SMEM>>>(
        pf, rw, rb, rg, rbe, rm, rv, f1, out, nullptr, nullptr, 256);
}

// round 12
// speedup vs baseline: 6.3310x; 1.9094x over previous
#include <cuda_runtime.h>
#include <cuda_bf16.h>
#include <cstddef>
#include <cstdint>

#define BN_EPS 1e-5f

// ---------------------------------------------------------------------------
// Scratch (device globals — no allocation allowed)
// ---------------------------------------------------------------------------
__device__ unsigned short g_qh[4 * 4096 * 64];   // q  [b][n][c] h/l
__device__ unsigned short g_ql[4 * 4096 * 64];
__device__ unsigned short g_kh[4 * 4096 * 64];   // k  [b][n][c]
__device__ unsigned short g_kl[4 * 4096 * 64];
__device__ unsigned short g_vh[4 * 64 * 4096];   // v  [b][c][n]
__device__ unsigned short g_vl[4 * 64 * 4096];
__device__ unsigned short g_x1h[4 * 4096 * 256]; // feature1 transposed [b][n][c]
__device__ unsigned short g_x1l[4 * 4096 * 256];
__device__ unsigned short g_x2h[4 * 4096 * 256]; // feature2 transposed [b][n][c]
__device__ unsigned short g_x2l[4 * 4096 * 256];
__device__ unsigned short g_fh[4 * 4096 * 64];   // attn out [b][n][c]
__device__ unsigned short g_fl[4 * 4096 * 64];
__device__ unsigned short g_wh[884736];          // prepped weights (h)
__device__ unsigned short g_wl[884736];          // prepped weights (l)
__device__ float g_bn[2048];                     // [conv][oc][2] inv,bias

// ---------------------------------------------------------------------------
// PTX helpers (baseline sm_80+ features only — harness compiles via compute_103)
// ---------------------------------------------------------------------------
__device__ __forceinline__ uint32_t smem_u32(const void* p) {
    uint32_t a;
    asm("{ .reg .u64 t; cvta.to.shared.u64 t, %1; cvt.u32.u64 %0, t; }"
        : "=r"(a) : "l"(p));
    return a;
}
__device__ __forceinline__ void ldm_x2(uint32_t* r, uint32_t a) {
    asm volatile("ldmatrix.sync.aligned.m8n8.x2.shared.b16 {%0,%1}, [%2];"
                 : "=r"(r[0]), "=r"(r[1]) : "r"(a));
}
__device__ __forceinline__ void ldm_x4(uint32_t* r, uint32_t a) {
    asm volatile("ldmatrix.sync.aligned.m8n8.x4.shared.b16 {%0,%1,%2,%3}, [%4];"
                 : "=r"(r[0]), "=r"(r[1]), "=r"(r[2]), "=r"(r[3]) : "r"(a));
}
__device__ __forceinline__ void mma16816(float* d, const uint32_t* a, const uint32_t* b) {
    asm volatile("mma.sync.aligned.m16n8k16.row.col.f32.bf16.bf16.f32 "
                 "{%0,%1,%2,%3}, {%4,%5,%6,%7}, {%8,%9}, {%0,%1,%2,%3};"
                 : "+f"(d[0]), "+f"(d[1]), "+f"(d[2]), "+f"(d[3])
                 : "r"(a[0]), "r"(a[1]), "r"(a[2]), "r"(a[3]),
                   "r"(b[0]), "r"(b[1]));
}
__device__ __forceinline__ uint32_t pack_bf16x2(float lo, float hi) {
    uint32_t r;
    asm("cvt.rn.bf16x2.f32 %0, %1, %2;" : "=r"(r) : "f"(hi), "f"(lo));
    return r;
}
__device__ __forceinline__ void split_bf16(float y, unsigned short& h, unsigned short& l) {
    __nv_bfloat16 hb = __float2bfloat16(y);
    float r = y - __bfloat162float(hb);
    __nv_bfloat16 lb = __float2bfloat16(r);
    h = __bfloat16_as_ushort(hb);
    l = __bfloat16_as_ushort(lb);
}

// ---------------------------------------------------------------------------
// Prep kernels (run once per launch, cheap)
// ---------------------------------------------------------------------------
// Transpose + split features: [b][c][n] fp32 -> [b][n][c] bf16 h/l.
// grid (128 n-tiles, 8 c-tiles, 4 b), block 256.
__global__ void prep_x(const float* __restrict__ f1, const float* __restrict__ f2)
{
    __shared__ float t1[32][33], t2[32][33];
    const int b = blockIdx.z, c0 = blockIdx.y << 5, n0 = blockIdx.x << 5;
    const int tid = threadIdx.x;
    const int a = tid >> 5, e = tid & 31;
#pragma unroll
    for (int i = 0; i < 4; i++) {
        int cl = a + (i << 3);
        size_t src = (((size_t)(b * 256 + c0 + cl)) << 12) + n0 + e;
        t1[cl][e] = f1[src];
        t2[cl][e] = f2[src];
    }
    __syncthreads();
#pragma unroll
    for (int i = 0; i < 4; i++) {
        int nl = a + (i << 3);
        size_t dst = ((size_t)((b << 12) + n0 + nl)) * 256 + c0 + e;
        unsigned short h, l;
        split_bf16(t1[e][nl], h, l);
        g_x1h[dst] = h; g_x1l[dst] = l;
        split_bf16(t2[e][nl], h, l);
        g_x2h[dst] = h; g_x2l[dst] = l;
    }
}

// Split + relayout weights into smem-ready tiles:
// dst = conv*221184 + (ocg*nch+chunk)*13824 + (off*64+oc)*24 + icl
__global__ void prep_w(const float* __restrict__ w, int conv, int CIN, int OCG)
{
    const int nch = CIN >> 4;
    const int total = OCG * nch * 9216;
    const int base = conv * 221184;
    for (int i = blockIdx.x * 256 + threadIdx.x; i < total; i += gridDim.x * 256) {
        int icl = i & 15;
        int oc = (i >> 4) & 63;
        int off = (i >> 10) % 9;
        int t = i / 9216;
        int chunk = t % nch;
        int ocg = t / nch;
        float v = w[(((size_t)(ocg * 64 + oc)) * CIN + (chunk << 4) + icl) * 9 + off];
        unsigned short h, l;
        split_bf16(v, h, l);
        int dst = base + (ocg * nch + chunk) * 13824 + ((off << 6) + oc) * 24 + icl;
        g_wh[dst] = h; g_wl[dst] = l;
    }
}

// Fold BN params: g_bn[conv*512 + oc*2] = inv, +1 = bias. launch <<<2,256>>>.
__global__ void prep_bn(
    const float* qb, const float* qg, const float* qbe, const float* qm, const float* qvv,
    const float* kb, const float* kg, const float* kbe, const float* km, const float* kvv,
    const float* vb, const float* vg, const float* vbe, const float* vm, const float* vvv,
    const float* rb, const float* rg, const float* rbe, const float* rm, const float* rvv)
{
    int t = blockIdx.x * 256 + threadIdx.x;
    const float *cb, *cg, *cbe, *cm, *cvr;
    int conv, oc;
    if (t < 64)       { conv = 0; oc = t;       cb = qb; cg = qg; cbe = qbe; cm = qm; cvr = qvv; }
    else if (t < 128) { conv = 1; oc = t - 64;  cb = kb; cg = kg; cbe = kbe; cm = km; cvr = kvv; }
    else if (t < 192) { conv = 2; oc = t - 128; cb = vb; cg = vg; cbe = vbe; cm = vm; cvr = vvv; }
    else if (t < 448) { conv = 3; oc = t - 192; cb = rb; cg = rg; cbe = rbe; cm = rm; cvr = rvv; }
    else return;
    float inv = cg[oc] * rsqrtf(cvr[oc] + BN_EPS);
    g_bn[conv * 512 + oc * 2] = inv;
    g_bn[conv * 512 + oc * 2 + 1] = fmaf(cb[oc], inv, cbe[oc] - cm[oc] * inv);
}

// ---------------------------------------------------------------------------
// Conv mainloop: implicit GEMM, 9 shifted taps, 16-ic chunks, 3-pass bf16.
// Inputs pre-split [b][n][CIN]; weights pre-tiled; staging = vector copies.
// Tile: 128 pixels (2 rows) x 64 oc per block, 8 warps.
// ---------------------------------------------------------------------------
#define XTILE 10560   // 4*66 cells * 40-elem stride
#define WTILE 13824   // 9*64 rows * 24-elem stride
#define CONV_SMEM (2 * (XTILE + WTILE) * 2 + 512)

__device__ __forceinline__ void conv_core(
    const unsigned short* __restrict__ inh,
    const unsigned short* __restrict__ inl,
    int CIN, int wbase, int b, int r0,
    unsigned short* XH, unsigned short* XL,
    unsigned short* WH, unsigned short* WL,
    float acc[8][4])
{
    const int tid = threadIdx.x;
    const int lane = tid & 31, warp = tid >> 5, l4 = lane & 15;
    const int yy = warp >> 2, xb = (warp & 3) << 4;
    const uint32_t xhb = smem_u32(XH), xlb = smem_u32(XL);
    const uint32_t whb = smem_u32(WH), wlb = smem_u32(WL);

    // zero halo border cells (hx = 0, 65) once — never rewritten
    for (int i = tid; i < 128; i += 256) {
        int hy = i >> 5, r = i & 31;
        int hx = (r >> 4) ? 65 : 0, icl = r & 15;
        int si = (hy * 66 + hx) * 40 + icl;
        XH[si] = 0; XL[si] = 0;
    }

    const int nch = CIN >> 4;
    const int gy = r0 - 1 + (tid >> 6);        // this thread's halo row
    const int gx = tid & 63;
    const bool inb = (unsigned)gy < 64u;
    const size_t cellbase = inb ? ((size_t)((b << 12) + (gy << 6) + gx)) * CIN : 0;
    const int si0 = ((tid >> 6) * 66 + 1 + gx) * 40;

    for (int chunk = 0; chunk < nch; chunk++) {
        __syncthreads();
        // input: one 4x64 cell per thread; 16 contiguous ic = 2 uint4 per buffer
        {
            uint4 h0 = {0,0,0,0}, h1 = {0,0,0,0}, l0 = {0,0,0,0}, l1 = {0,0,0,0};
            if (inb) {
                const uint4* ph = (const uint4*)(inh + cellbase + (chunk << 4));
                const uint4* pl = (const uint4*)(inl + cellbase + (chunk << 4));
                h0 = ph[0]; h1 = ph[1]; l0 = pl[0]; l1 = pl[1];
            }
            *(uint4*)(XH + si0) = h0; *(uint4*)(XH + si0 + 8) = h1;
            *(uint4*)(XL + si0) = l0; *(uint4*)(XL + si0 + 8) = l1;
        }
        // weights: straight contiguous copy of the prepped tile
        {
            const uint4* swh = (const uint4*)(g_wh + wbase + chunk * 13824);
            const uint4* swl = (const uint4*)(g_wl + wbase + chunk * 13824);
            uint4* dwh = (uint4*)WH;
            uint4* dwl = (uint4*)WL;
            for (int i = tid; i < 1728; i += 256) { dwh[i] = swh[i]; dwl[i] = swl[i]; }
        }
        __syncthreads();

#pragma unroll
        for (int ky = 0; ky < 3; ky++) {
#pragma unroll
            for (int kx = 0; kx < 3; kx++) {
                uint32_t aro = (uint32_t)((yy + ky) * 66 + xb + l4 + kx) * 80 +
                               ((lane >> 4) << 4);
                uint32_t afh[4], afl[4];
                ldm_x4(afh, xhb + aro);
                ldm_x4(afl, xlb + aro);
                uint32_t bro = (uint32_t)((ky * 3 + kx) * 64 + l4) * 48 +
                               ((lane >> 4) << 4);
#pragma unroll
                for (int g = 0; g < 4; g++) {
                    uint32_t bh[4], bl[4];
                    ldm_x4(bh, whb + bro + g * 768);
                    ldm_x4(bl, wlb + bro + g * 768);
                    uint32_t b0h[2] = {bh[0], bh[2]}, b1h[2] = {bh[1], bh[3]};
                    uint32_t b0l[2] = {bl[0], bl[2]}, b1l[2] = {bl[1], bl[3]};
                    mma16816(acc[2 * g],     afh, b0h);
                    mma16816(acc[2 * g],     afl, b0h);
                    mma16816(acc[2 * g],     afh, b0l);
                    mma16816(acc[2 * g + 1], afh, b1h);
                    mma16816(acc[2 * g + 1], afl, b1h);
                    mma16816(acc[2 * g + 1], afh, b1l);
                }
            }
        }
    }
}

// q/k/v fused: blockIdx.y = conv index (0=q from f2, 1=k from f1, 2=v from f1)
__global__ void __launch_bounds__(256, 2) conv_qkv_mma()
{
    extern __shared__ unsigned short smu[];
    unsigned short* XH = smu;
    unsigned short* XL = XH + XTILE;
    unsigned short* WH = XL + XTILE;
    unsigned short* WL = WH + WTILE;
    float* BN = (float*)(WL + WTILE);

    const int cidx = blockIdx.y;
    const int b = blockIdx.z;
    const int r0 = blockIdx.x << 1;
    const int n0 = blockIdx.x << 7;
    const int tid = threadIdx.x;

    if (tid < 64) {
        BN[tid * 2]     = g_bn[cidx * 512 + tid * 2];
        BN[tid * 2 + 1] = g_bn[cidx * 512 + tid * 2 + 1];
    }

    const unsigned short* inh = (cidx == 0) ? g_x2h : g_x1h;
    const unsigned short* inl = (cidx == 0) ? g_x2l : g_x1l;

    float acc[8][4];
#pragma unroll
    for (int nc = 0; nc < 8; nc++)
#pragma unroll
        for (int k = 0; k < 4; k++) acc[nc][k] = 0.f;

    conv_core(inh, inl, 256, cidx * 221184, b, r0, XH, XL, WH, WL, acc);

    const int lane = tid & 31, warp = tid >> 5;
    const int gid = lane >> 2, tg = lane & 3;
    const int p0 = n0 + (warp << 4) + gid, p1 = p0 + 8;

    unsigned short *outh, *outl;
    if (cidx == 0)      { outh = g_qh; outl = g_ql; }
    else if (cidx == 1) { outh = g_kh; outl = g_kl; }
    else                { outh = g_vh; outl = g_vl; }

#pragma unroll
    for (int nc = 0; nc < 8; nc++) {
        int c0 = nc * 8 + tg * 2;
        float i0 = BN[c0 * 2],     bb0 = BN[c0 * 2 + 1];
        float i1 = BN[c0 * 2 + 2], bb1 = BN[c0 * 2 + 3];
        float y00 = fmaxf(fmaf(acc[nc][0], i0, bb0), 0.f);
        float y01 = fmaxf(fmaf(acc[nc][1], i1, bb1), 0.f);
        float y10 = fmaxf(fmaf(acc[nc][2], i0, bb0), 0.f);
        float y11 = fmaxf(fmaf(acc[nc][3], i1, bb1), 0.f);
        if (cidx < 2) {   // [n][c] split pairs
            unsigned short h00, l00, h01, l01, h10, l10, h11, l11;
            split_bf16(y00, h00, l00); split_bf16(y01, h01, l01);
            split_bf16(y10, h10, l10); split_bf16(y11, h11, l11);
            size_t a0 = ((size_t)((b << 12) + p0)) * 64 + c0;
            size_t a1 = ((size_t)((b << 12) + p1)) * 64 + c0;
            *(uint32_t*)(outh + a0) = ((uint32_t)h01 << 16) | h00;
            *(uint32_t*)(outl + a0) = ((uint32_t)l01 << 16) | l00;
            *(uint32_t*)(outh + a1) = ((uint32_t)h11 << 16) | h10;
            *(uint32_t*)(outl + a1) = ((uint32_t)l11 << 16) | l10;
        } else {          // v: [c][n]
            unsigned short h, l;
            size_t ga = ((size_t)(b * 64 + c0)) << 12, gb = ga + 4096;
            split_bf16(y00, h, l); outh[ga + p0] = h; outl[ga + p0] = l;
            split_bf16(y01, h, l); outh[gb + p0] = h; outl[gb + p0] = l;
            split_bf16(y10, h, l); outh[ga + p1] = h; outl[ga + p1] = l;
            split_bf16(y11, h, l); outh[gb + p1] = h; outl[gb + p1] = l;
        }
    }
}

// final conv: blockIdx.y = oc-group (0..3), input g_fh/g_fl [b][n][64]
__global__ void __launch_bounds__(256, 2) conv_final_mma(const float* __restrict__ resid,
                                                         float* __restrict__ out)
{
    extern __shared__ unsigned short smu[];
    unsigned short* XH = smu;
    unsigned short* XL = XH + XTILE;
    unsigned short* WH = XL + XTILE;
    unsigned short* WL = WH + WTILE;
    float* BN = (float*)(WL + WTILE);

    const int ocg = blockIdx.y;
    const int b = blockIdx.z;
    const int r0 = blockIdx.x << 1;
    const int n0 = blockIdx.x << 7;
    const int tid = threadIdx.x;

    if (tid < 64) {
        BN[tid * 2]     = g_bn[3 * 512 + ocg * 128 + tid * 2];
        BN[tid * 2 + 1] = g_bn[3 * 512 + ocg * 128 + tid * 2 + 1];
    }

    float acc[8][4];
#pragma unroll
    for (int nc = 0; nc < 8; nc++)
#pragma unroll
        for (int k = 0; k < 4; k++) acc[nc][k] = 0.f;

    conv_core(g_fh, g_fl, 64, 3 * 221184 + ocg * 55296, b, r0, XH, XL, WH, WL, acc);

    const int lane = tid & 31, warp = tid >> 5;
    const int gid = lane >> 2, tg = lane & 3;
    const int p0 = n0 + (warp << 4) + gid, p1 = p0 + 8;

#pragma unroll
    for (int nc = 0; nc < 8; nc++) {
        int c0 = nc * 8 + tg * 2;
        float i0 = BN[c0 * 2],     bb0 = BN[c0 * 2 + 1];
        float i1 = BN[c0 * 2 + 2], bb1 = BN[c0 * 2 + 3];
        float y00 = fmaxf(fmaf(acc[nc][0], i0, bb0), 0.f);
        float y01 = fmaxf(fmaf(acc[nc][1], i1, bb1), 0.f);
        float y10 = fmaxf(fmaf(acc[nc][2], i0, bb0), 0.f);
        float y11 = fmaxf(fmaf(acc[nc][3], i1, bb1), 0.f);
        size_t ga = ((size_t)(b * 256 + (ocg << 6) + c0)) << 12;
        size_t gb = ga + 4096;
        out[ga + p0] = y00 + resid[ga + p0];
        out[gb + p0] = y01 + resid[gb + p0];
        out[ga + p1] = y10 + resid[ga + p1];
        out[gb + p1] = y11 + resid[gb + p1];
    }
}

// ---------------------------------------------------------------------------
// Flash attention with mma.sync bf16 + fp32 hi/lo splitting (R8/R11 core,
// verified; only the epilogue changed: writes split [n][c] h/l for the
// final conv's cheap staging path).
// ---------------------------------------------------------------------------
#define QS 72  // smem row stride (bf16 elems), 144 bytes

__global__ void __launch_bounds__(256) attn_mma_kernel()
{
    extern __shared__ unsigned short smu[];
    unsigned short* Qh = smu;            // 128 x QS
    unsigned short* Ql = smu + 9216;
    unsigned short* Kh = smu + 18432;    // 64 x QS  [key][chan]
    unsigned short* Kl = smu + 23040;
    unsigned short* Vh = smu + 27648;    // 64 x QS  [chan][key]
    unsigned short* Vl = smu + 32256;

    const int tid  = threadIdx.x;
    const int lane = tid & 31;
    const int warp = tid >> 5;
    const int gid  = lane >> 2, tg = lane & 3;
    const int b  = blockIdx.y;
    const int n0 = blockIdx.x << 7;
    const int mbase = warp << 4;

    // ---- load Q tile (128x64, hi/lo) into padded smem ----
    {
        int r = tid >> 1, h = (tid & 1) << 5;
        size_t src = ((size_t)(b * 4096 + n0 + r)) * 64 + h;
        const uint4* sh = (const uint4*)(g_qh + src);
        const uint4* sl = (const uint4*)(g_ql + src);
        uint4* dh = (uint4*)(Qh + r * QS + h);
        uint4* dl = (uint4*)(Ql + r * QS + h);
#pragma unroll
        for (int i = 0; i < 4; i++) { dh[i] = sh[i]; dl[i] = sl[i]; }
    }
    __syncthreads();

    // ---- Q fragments, resident for whole kernel ----
    uint32_t qfh[4][4], qfl[4][4];
    {
        uint32_t qhb = smem_u32(Qh), qlb = smem_u32(Ql);
        uint32_t ro = (uint32_t)(mbase + (lane & 15)) * (QS * 2) + ((lane >> 4) << 4);
#pragma unroll
        for (int i = 0; i < 4; i++) {
            ldm_x4(qfh[i], qhb + ro + i * 32);
            ldm_x4(qfl[i], qlb + ro + i * 32);
        }
    }

    const uint32_t khb = smem_u32(Kh), klb = smem_u32(Kl);
    const uint32_t vhb = smem_u32(Vh), vlb = smem_u32(Vl);
    const int l4 = lane & 15;
    const uint32_t bro = (uint32_t)(l4 & 7) * (QS * 2) + ((l4 >> 3) << 4);

    float O[8][4];
    float mi0 = -1e30f, mi1 = -1e30f, li0 = 0.f, li1 = 0.f;
#pragma unroll
    for (int j = 0; j < 8; j++)
#pragma unroll
        for (int k = 0; k < 4; k++) O[j][k] = 0.f;

    for (int t = 0; t < 64; t++) {
        __syncthreads();

        {
            int r = tid >> 2, s = (tid & 3) << 4;
            size_t kb = ((size_t)(b * 4096 + (t << 6) + r)) * 64 + s;
            const uint4* skh = (const uint4*)(g_kh + kb);
            const uint4* skl = (const uint4*)(g_kl + kb);
            uint4* dkh = (uint4*)(Kh + r * QS + s);
            uint4* dkl = (uint4*)(Kl + r * QS + s);
            dkh[0] = skh[0]; dkh[1] = skh[1];
            dkl[0] = skl[0]; dkl[1] = skl[1];
            size_t vb = (((size_t)(b * 64 + r)) << 12) + (t << 6) + s;
            const uint4* svh = (const uint4*)(g_vh + vb);
            const uint4* svl = (const uint4*)(g_vl + vb);
            uint4* dvh = (uint4*)(Vh + r * QS + s);
            uint4* dvl = (uint4*)(Vl + r * QS + s);
            dvh[0] = svh[0]; dvh[1] = svh[1];
            dvl[0] = svl[0]; dvl[1] = svl[1];
        }
        __syncthreads();

        float sacc[8][4];
#pragma unroll
        for (int j = 0; j < 8; j++)
#pragma unroll
            for (int k = 0; k < 4; k++) sacc[j][k] = 0.f;

#pragma unroll
        for (int j = 0; j < 8; j++) {
#pragma unroll
            for (int i = 0; i < 4; i++) {
                uint32_t off = (uint32_t)(8 * j) * (QS * 2) + bro + i * 32;
                uint32_t bh[2], bl[2];
                ldm_x2(bh, khb + off);
                ldm_x2(bl, klb + off);
                mma16816(sacc[j], qfh[i], bh);
                mma16816(sacc[j], qfl[i], bh);
                mma16816(sacc[j], qfh[i], bl);
            }
        }

        float rm0 = -1e30f, rm1 = -1e30f;
#pragma unroll
        for (int j = 0; j < 8; j++) {
            rm0 = fmaxf(rm0, fmaxf(sacc[j][0], sacc[j][1]));
            rm1 = fmaxf(rm1, fmaxf(sacc[j][2], sacc[j][3]));
        }
        rm0 = fmaxf(rm0, __shfl_xor_sync(0xffffffffu, rm0, 1));
        rm0 = fmaxf(rm0, __shfl_xor_sync(0xffffffffu, rm0, 2));
        rm1 = fmaxf(rm1, __shfl_xor_sync(0xffffffffu, rm1, 1));
        rm1 = fmaxf(rm1, __shfl_xor_sync(0xffffffffu, rm1, 2));

        float mn0 = fmaxf(mi0, rm0), mn1 = fmaxf(mi1, rm1);
        float c0 = __expf(mi0 - mn0), c1 = __expf(mi1 - mn1);
        mi0 = mn0; mi1 = mn1;

        float rs0 = 0.f, rs1 = 0.f;
        uint32_t ph[16], pl[16];
#pragma unroll
        for (int j = 0; j < 8; j++) {
            float p00 = __expf(sacc[j][0] - mi0);
            float p01 = __expf(sacc[j][1] - mi0);
            float p10 = __expf(sacc[j][2] - mi1);
            float p11 = __expf(sacc[j][3] - mi1);
            rs0 += p00 + p01;
            rs1 += p10 + p11;
            uint32_t h0 = pack_bf16x2(p00, p01);
            uint32_t h1 = pack_bf16x2(p10, p11);
            ph[2 * j]     = h0;
            ph[2 * j + 1] = h1;
            float r00 = p00 - __uint_as_float(h0 << 16);
            float r01 = p01 - __uint_as_float(h0 & 0xffff0000u);
            float r10 = p10 - __uint_as_float(h1 << 16);
            float r11 = p11 - __uint_as_float(h1 & 0xffff0000u);
            pl[2 * j]     = pack_bf16x2(r00, r01);
            pl[2 * j + 1] = pack_bf16x2(r10, r11);
        }
        rs0 += __shfl_xor_sync(0xffffffffu, rs0, 1);
        rs0 += __shfl_xor_sync(0xffffffffu, rs0, 2);
        rs1 += __shfl_xor_sync(0xffffffffu, rs1, 1);
        rs1 += __shfl_xor_sync(0xffffffffu, rs1, 2);
        li0 = li0 * c0 + rs0;
        li1 = li1 * c1 + rs1;

#pragma unroll
        for (int j = 0; j < 8; j++) {
            O[j][0] *= c0; O[j][1] *= c0;
            O[j][2] *= c1; O[j][3] *= c1;
        }

#pragma unroll
        for (int j = 0; j < 8; j++) {
#pragma unroll
            for (int i = 0; i < 4; i++) {
                uint32_t off = (uint32_t)(8 * j) * (QS * 2) + bro + i * 32;
                uint32_t bvh[2], bvl[2];
                ldm_x2(bvh, vhb + off);
                ldm_x2(bvl, vlb + off);
                mma16816(O[j], &ph[4 * i], bvh);
                mma16816(O[j], &pl[4 * i], bvh);
                mma16816(O[j], &ph[4 * i], bvl);
            }
        }
    }

    // ---- normalize, split, write f as [b][n][c] h/l ----
    {
        float i0 = 1.f / li0, i1 = 1.f / li1;
        int r0n = n0 + mbase + gid, r1n = r0n + 8;
        size_t a0 = ((size_t)((b << 12) + r0n)) * 64;
        size_t a1 = ((size_t)((b << 12) + r1n)) * 64;
#pragma unroll
        for (int j = 0; j < 8; j++) {
            int c = 8 * j + 2 * tg;
            unsigned short h0, l0, h1, l1;
            split_bf16(O[j][0] * i0, h0, l0);
            split_bf16(O[j][1] * i0, h1, l1);
            *(uint32_t*)(g_fh + a0 + c) = ((uint32_t)h1 << 16) | h0;
            *(uint32_t*)(g_fl + a0 + c) = ((uint32_t)l1 << 16) | l0;
            split_bf16(O[j][2] * i1, h0, l0);
            split_bf16(O[j][3] * i1, h1, l1);
            *(uint32_t*)(g_fh + a1 + c) = ((uint32_t)h1 << 16) | h0;
            *(uint32_t*)(g_fl + a1 + c) = ((uint32_t)l1 << 16) | l0;
        }
    }
}

// ---------------------------------------------------------------------------
extern "C" void kernel_launch(void* const* d_in, const int* in_sizes, int n_in,
                              void* d_out, int out_size)
{
    (void)in_sizes; (void)n_in; (void)out_size;

    const float* f1  = (const float*)d_in[0];
    const float* f2  = (const float*)d_in[1];
    const float* qw  = (const float*)d_in[2];
    const float* qb  = (const float*)d_in[3];
    const float* qg  = (const float*)d_in[4];
    const float* qbe = (const float*)d_in[5];
    const float* qm  = (const float*)d_in[6];
    const float* qv  = (const float*)d_in[7];
    const float* kw  = (const float*)d_in[8];
    const float* kb  = (const float*)d_in[9];
    const float* kg  = (const float*)d_in[10];
    const float* kbe = (const float*)d_in[11];
    const float* km  = (const float*)d_in[12];
    const float* kv  = (const float*)d_in[13];
    const float* vw  = (const float*)d_in[14];
    const float* vb  = (const float*)d_in[15];
    const float* vg  = (const float*)d_in[16];
    const float* vbe = (const float*)d_in[17];
    const float* vm  = (const float*)d_in[18];
    const float* vv  = (const float*)d_in[19];
    const float* rw  = (const float*)d_in[20];
    const float* rb  = (const float*)d_in[21];
    const float* rg  = (const float*)d_in[22];
    const float* rbe = (const float*)d_in[23];
    const float* rm  = (const float*)d_in[24];
    const float* rv  = (const float*)d_in[25];
    float* out = (float*)d_out;

    // prep: split/transposed inputs, tiled split weights, folded BN
    prep_x<<<dim3(128, 8, 4), 256>>>(f1, f2);
    prep_w<<<144, 256>>>(qw, 0, 256, 1);
    prep_w<<<144, 256>>>(kw, 1, 256, 1);
    prep_w<<<144, 256>>>(vw, 2, 256, 1);
    prep_w<<<144, 256>>>(rw, 3, 64, 4);
    prep_bn<<<2, 256>>>(qb, qg, qbe, qm, qv,
                        kb, kg, kbe, km, kv,
                        vb, vg, vbe, vm, vv,
                        rb, rg, rbe, rm, rv);

    cudaFuncSetAttribute(conv_qkv_mma,
                         cudaFuncAttributeMaxDynamicSharedMemorySize, CONV_SMEM);
    cudaFuncSetAttribute(conv_final_mma,
                         cudaFuncAttributeMaxDynamicSharedMemorySize, CONV_SMEM);

    // fused q/k/v convs (384 blocks, 2 resident/SM)
    conv_qkv_mma<<<dim3(32, 3, 4), 256, CONV_SMEM>>>();

    const int attn_smem = 36864 * (int)sizeof(unsigned short);  // 73728 B
    cudaFuncSetAttribute(attn_mma_kernel,
                         cudaFuncAttributeMaxDynamicSharedMemorySize, attn_smem);
    attn_mma_kernel<<<dim3(32, 4), 256, attn_smem>>>();

    // out = feature1 + conv_bn_relu(f)
    conv_final_mma<<<dim3(32, 4, 4), 256, CONV_SMEM>>>(f1, out);
}